// round 9
// baseline (speedup 1.0000x reference)
#include <cuda_runtime.h>
#include <cuda_fp16.h>
#include <cstdint>

// GIN: 5 layers, N=20000 nodes, E=320000 edges, HIDDEN=64, M=8.
//  - CSR build per launch (histogram + scan + fill).
//  - h fp16 ping-pong buffers (g_hbuf/g_h2), L2-resident.
//  - k_layer (fused, per layer): CSR gather + BN affine -> smem z fp16 ->
//    HMMA GEMM1+relu -> HMMA GEMM2+relu -> h fp16 out + BN stats.
//  - BN folded to per-channel affine; finalize kernel per layer.

#define N_NODES 20000
#define N_EDGES 320000
#define HID 64
#define MDIM 8
#define FEAT (HID*MDIM)   // 512 elements per node

typedef unsigned long long ull;

// ---------------- device scratch ----------------
__device__ __half g_hbuf[N_NODES * FEAT];   // h ping
__device__ __half g_h2[N_NODES * FEAT];     // h pong
__device__ int    g_rowptr[N_NODES + 1];
__device__ int    g_count[N_NODES];
__device__ int    g_fill[N_NODES];
__device__ int    g_srce[N_EDGES];
__device__ float  g_stats[5 * 128];         // per layer: sum[64], sumsq[64]
__device__ float  g_affine[5 * 128];        // per layer: scale[64], shift[64]
__device__ ull    g_Wt2p[4096];             // W2 layer 0 (layer0 FFMA2 path), [c][o] pairs
__device__ __half g_W1h[4 * 4096];          // W1 layers 1..4, [o][c] fp16
__device__ __half g_W2h[5 * 4096];          // W2 layers 0..4, [o][c] fp16
__device__ float  g_pool[FEAT];
__device__ int    g_is64;

// ---------------- helpers ----------------
__device__ __forceinline__ ull pk2(float a, float b) {
    ull r; asm("mov.b64 %0, {%1, %2};" : "=l"(r) : "f"(a), "f"(b)); return r;
}
__device__ __forceinline__ float2 upk(ull v) {
    float2 r; asm("mov.b64 {%0, %1}, %2;" : "=f"(r.x), "=f"(r.y) : "l"(v)); return r;
}
__device__ __forceinline__ void fma2(ull& a, ull b, ull c) {
    asm("fma.rn.f32x2 %0, %1, %2, %0;" : "+l"(a) : "l"(b), "l"(c));
}
__device__ __forceinline__ uint32_t smem_u32(const void* p) {
    return (uint32_t)__cvta_generic_to_shared(p);
}
__device__ __forceinline__ void ldmA(unsigned a[4], uint32_t addr) {
    asm volatile("ldmatrix.sync.aligned.m8n8.x4.shared.b16 {%0,%1,%2,%3}, [%4];"
        : "=r"(a[0]), "=r"(a[1]), "=r"(a[2]), "=r"(a[3]) : "r"(addr));
}
__device__ __forceinline__ void ldmBt(unsigned b[2], uint32_t addr) {
    asm volatile("ldmatrix.sync.aligned.m8n8.x2.trans.shared.b16 {%0,%1}, [%2];"
        : "=r"(b[0]), "=r"(b[1]) : "r"(addr));
}
__device__ __forceinline__ void mma16816(float d[4], const unsigned a[4], const unsigned b[2]) {
    asm volatile("mma.sync.aligned.m16n8k16.row.col.f32.f16.f16.f32 "
        "{%0,%1,%2,%3}, {%4,%5,%6,%7}, {%8,%9}, {%0,%1,%2,%3};"
        : "+f"(d[0]), "+f"(d[1]), "+f"(d[2]), "+f"(d[3])
        : "r"(a[0]), "r"(a[1]), "r"(a[2]), "r"(a[3]), "r"(b[0]), "r"(b[1]));
}

// ---------------- setup kernels ----------------
__global__ void k_init(const void* ei) {
    __shared__ int s_ok;
    if (threadIdx.x == 0) s_ok = 1;
    __syncthreads();
    int i = blockIdx.x * blockDim.x + threadIdx.x;
    if (i < N_NODES) { g_count[i] = 0; g_fill[i] = 0; }
    if (i < 5 * 128) g_stats[i] = 0.f;
    if (i < FEAT)    g_pool[i] = 0.f;
    // dtype detect: first 64 values as u64; any >= N_NODES => int32 layout
    if (blockIdx.x == 0 && threadIdx.x < 64) {
        if (((const ull*)ei)[threadIdx.x] >= (ull)N_NODES) atomicExch(&s_ok, 0);
    }
    __syncthreads();
    if (blockIdx.x == 0 && threadIdx.x == 0) g_is64 = s_ok;
}

__device__ __forceinline__ int edge_at(const void* ei, int idx) {
    return g_is64 ? (int)((const long long*)ei)[idx] : ((const int*)ei)[idx];
}

__global__ void k_hist(const void* ei) {
    int e = blockIdx.x * blockDim.x + threadIdx.x;
    if (e >= N_EDGES) return;
    atomicAdd(&g_count[edge_at(ei, N_EDGES + e)], 1);
}

__global__ void k_scan() {   // 1 block, 1024 threads, exclusive prefix over 20000
    __shared__ int s[1024];
    const int CH = 20;
    int t = threadIdx.x;
    int base = t * CH;
    int vals[CH];
    int local = 0;
#pragma unroll
    for (int j = 0; j < CH; j++) {
        int i = base + j;
        int v = (i < N_NODES) ? g_count[i] : 0;
        vals[j] = local; local += v;
    }
    s[t] = local;
    __syncthreads();
    for (int off = 1; off < 1024; off <<= 1) {
        int v = s[t];
        int add = (t >= off) ? s[t - off] : 0;
        __syncthreads();
        s[t] = v + add;
        __syncthreads();
    }
    int bb = (t == 0) ? 0 : s[t - 1];
#pragma unroll
    for (int j = 0; j < CH; j++) {
        int i = base + j;
        if (i < N_NODES) g_rowptr[i] = bb + vals[j];
    }
    if (t == 1023) g_rowptr[N_NODES] = s[1023];
}

__global__ void k_fill(const void* ei) {
    int e = blockIdx.x * blockDim.x + threadIdx.x;
    if (e >= N_EDGES) return;
    int srcv = edge_at(ei, e);
    int d    = edge_at(ei, N_EDGES + e);
    int pos  = g_rowptr[d] + atomicAdd(&g_fill[d], 1);
    g_srce[pos] = srcv;
}

// weight prep: fp16 copies of W1 (1..4) / W2 (0..4) [o][c]; fp32 pairs for layer0 W2.
__global__ void k_prep(const float* __restrict__ w1, const float* __restrict__ w2) {
    int idx = blockIdx.x * blockDim.x + threadIdx.x;
    if (idx < 4 * 4096) {
        g_W1h[idx] = __float2half(w1[idx]);
    } else if (idx < 9 * 4096) {
        int j = idx - 4 * 4096;
        float v = w2[j];
        g_W2h[j] = __float2half(v);
        if (j < 4096) {
            int o = j >> 6, c = j & 63;
            g_Wt2p[(c << 6) + o] = pk2(v, v);
        }
    }
}

// ---------------- layer0 FFMA2 GEMM core (once per launch) ----------------
__device__ __forceinline__ void gemm64(const float* sIn, const ull* __restrict__ Wp,
                                       ull acc[16]) {
#pragma unroll
    for (int i = 0; i < 16; i++) acc[i] = 0ULL;
#pragma unroll 8
    for (int c = 0; c < 64; c++) {
        ulonglong2 wa = *(const ulonglong2*)(Wp + (c << 6));
        ulonglong2 wb = *(const ulonglong2*)(Wp + (c << 6) + 2);
        ulonglong2 za = *(const ulonglong2*)(sIn + (c << 3));
        ulonglong2 zb = *(const ulonglong2*)(sIn + (c << 3) + 4);
        ull w0 = wa.x, w1 = wa.y, w2 = wb.x, w3 = wb.y;
        ull z0 = za.x, z1 = za.y, z2 = zb.x, z3 = zb.y;
        fma2(acc[0],  w0, z0); fma2(acc[1],  w0, z1); fma2(acc[2],  w0, z2); fma2(acc[3],  w0, z3);
        fma2(acc[4],  w1, z0); fma2(acc[5],  w1, z1); fma2(acc[6],  w1, z2); fma2(acc[7],  w1, z3);
        fma2(acc[8],  w2, z0); fma2(acc[9],  w2, z1); fma2(acc[10], w2, z2); fma2(acc[11], w2, z3);
        fma2(acc[12], w3, z0); fma2(acc[13], w3, z1); fma2(acc[14], w3, z2); fma2(acc[15], w3, z3);
    }
}

__device__ __forceinline__ void epi2_l0(const ull acc[16], const float* sB2,
                                        __half* outh, int o0, float* sStats) {
#pragma unroll
    for (int r = 0; r < 4; r++) {
        int o = o0 + r;
        float b = sB2[o];
        float2 p0 = upk(acc[r * 4 + 0]), p1 = upk(acc[r * 4 + 1]);
        float2 p2 = upk(acc[r * 4 + 2]), p3 = upk(acc[r * 4 + 3]);
        float f0 = fmaxf(p0.x + b, 0.f), f1 = fmaxf(p0.y + b, 0.f);
        float f2 = fmaxf(p1.x + b, 0.f), f3 = fmaxf(p1.y + b, 0.f);
        float f4 = fmaxf(p2.x + b, 0.f), f5 = fmaxf(p2.y + b, 0.f);
        float f6 = fmaxf(p3.x + b, 0.f), f7 = fmaxf(p3.y + b, 0.f);
        __half2 h0 = __floats2half2_rn(f0, f1);
        __half2 h1 = __floats2half2_rn(f2, f3);
        __half2 h2 = __floats2half2_rn(f4, f5);
        __half2 h3 = __floats2half2_rn(f6, f7);
        uint4 hv;
        hv.x = *(unsigned*)&h0; hv.y = *(unsigned*)&h1;
        hv.z = *(unsigned*)&h2; hv.w = *(unsigned*)&h3;
        *(uint4*)(outh + o * 8) = hv;
        float s = f0 + f1 + f2 + f3 + f4 + f5 + f6 + f7;
        float q = f0*f0 + f1*f1 + f2*f2 + f3*f3 + f4*f4 + f5*f5 + f6*f6 + f7*f7;
        s += __shfl_xor_sync(0xffffffffu, s, 16);
        q += __shfl_xor_sync(0xffffffffu, q, 16);
        if ((threadIdx.x & 16) == 0) {
            atomicAdd(&sStats[o], s);
            atomicAdd(&sStats[64 + o], q);
        }
    }
}

// ---------------- layer 0 (IN_DIM=1) ----------------
__global__ void __launch_bounds__(128) k_layer0(
    const float* __restrict__ x, const float* __restrict__ w10,
    const float* __restrict__ b1, const float* __restrict__ b2) {
    __shared__ float sZ[8 * FEAT];
    __shared__ float sZ0[64];
    __shared__ float sStats[128];
    __shared__ float sB2[64];
    int t = threadIdx.x;
    sStats[t] = 0.f;
    if (t < 64) sB2[t] = b2[t];
    int g = t >> 4, l = t & 15;
    int n = (blockIdx.x << 3) + g;
    if (l < 8) {
        float a = x[n * 8 + l];
        int rs = g_rowptr[n], re = g_rowptr[n + 1];
        for (int e = rs; e < re; e++) a += x[g_srce[e] * 8 + l];
        sZ0[g * 8 + l] = a;
    }
    __syncthreads();
    int o0 = l << 2;
    float zz[8];
#pragma unroll
    for (int m = 0; m < 8; m++) zz[m] = sZ0[g * 8 + m];
#pragma unroll
    for (int r = 0; r < 4; r++) {
        int o = o0 + r;
        float w = w10[o], b = b1[o];
        float4 v0, v1;
        v0.x = fmaxf(w * zz[0] + b, 0.f); v0.y = fmaxf(w * zz[1] + b, 0.f);
        v0.z = fmaxf(w * zz[2] + b, 0.f); v0.w = fmaxf(w * zz[3] + b, 0.f);
        v1.x = fmaxf(w * zz[4] + b, 0.f); v1.y = fmaxf(w * zz[5] + b, 0.f);
        v1.z = fmaxf(w * zz[6] + b, 0.f); v1.w = fmaxf(w * zz[7] + b, 0.f);
        *(float4*)(sZ + (g << 9) + o * 8)     = v0;
        *(float4*)(sZ + (g << 9) + o * 8 + 4) = v1;
    }
    __syncthreads();
    ull acc[16];
    gemm64(sZ + (g << 9), g_Wt2p + o0, acc);
    epi2_l0(acc, sB2, g_hbuf + (size_t)n * FEAT, o0, sStats);
    __syncthreads();
    atomicAdd(&g_stats[t], sStats[t]);
}

// ---------------- fused layer (1..4): gather -> smem z -> HMMA MLP ----------------
__device__ __forceinline__ void acc8(float a[8], uint4 v) {
    float2 p;
    p = __half22float2(*(const __half2*)&v.x); a[0] += p.x; a[1] += p.y;
    p = __half22float2(*(const __half2*)&v.y); a[2] += p.x; a[3] += p.y;
    p = __half22float2(*(const __half2*)&v.z); a[4] += p.x; a[5] += p.y;
    p = __half22float2(*(const __half2*)&v.w); a[6] += p.x; a[7] += p.y;
}

__global__ void __launch_bounds__(512) k_layer(
    int layer, const float* __restrict__ b1, const float* __restrict__ b2) {
    __shared__ __half sW1[4096];
    __shared__ __half sW2[4096];
    __shared__ __half sZ[8 * FEAT];   // 8 node tiles [c64][m8] fp16, z -> y in place
    __shared__ float sStats[128];
    __shared__ float sAff[128];
    __shared__ float sB1[64], sB2[64];
    const __half* __restrict__ inb = (layer & 1) ? g_hbuf : g_h2;
    __half* __restrict__ outb      = (layer & 1) ? g_h2 : g_hbuf;
    int t = threadIdx.x;
    if (t < 128) { sStats[t] = 0.f; sAff[t] = g_affine[(layer - 1) * 128 + t]; }
    if (t < 64) { sB1[t] = b1[t]; sB2[t] = b2[t]; }
    // stage weights: 512 uint4 each, one per thread
    ((uint4*)sW1)[t] = ((const uint4*)(g_W1h + (size_t)(layer - 1) * 4096))[t];
    ((uint4*)sW2)[t] = ((const uint4*)(g_W2h + (size_t)layer * 4096))[t];
    __syncthreads();

    // ---- gather phase: 8 nodes x 64 channel-threads ----
    {
        const uint4* __restrict__ in = (const uint4*)inb;
        int node = t >> 6, l = t & 63;
        int n = (blockIdx.x << 3) + node;
        int rs = g_rowptr[n], re = g_rowptr[n + 1];
        float sc = sAff[l], sh = sAff[64 + l];
        float a[8] = {0,0,0,0,0,0,0,0}, b[8] = {0,0,0,0,0,0,0,0};
        acc8(a, in[(size_t)n * 64 + l]);   // self
        int e = rs;
        for (; e + 4 <= re; e += 4) {
            int s0 = g_srce[e], s1 = g_srce[e + 1], s2 = g_srce[e + 2], s3 = g_srce[e + 3];
            uint4 v0 = in[(size_t)s0 * 64 + l];
            uint4 v1 = in[(size_t)s1 * 64 + l];
            uint4 v2 = in[(size_t)s2 * 64 + l];
            uint4 v3 = in[(size_t)s3 * 64 + l];
            acc8(a, v0); acc8(b, v1); acc8(a, v2); acc8(b, v3);
        }
        for (; e < re; e++) acc8(a, in[(size_t)g_srce[e] * 64 + l]);
        float shd = sh * (float)(re - rs + 1);
        float f0 = sc * (a[0] + b[0]) + shd, f1 = sc * (a[1] + b[1]) + shd;
        float f2 = sc * (a[2] + b[2]) + shd, f3 = sc * (a[3] + b[3]) + shd;
        float f4 = sc * (a[4] + b[4]) + shd, f5 = sc * (a[5] + b[5]) + shd;
        float f6 = sc * (a[6] + b[6]) + shd, f7 = sc * (a[7] + b[7]) + shd;
        __half2 h0 = __floats2half2_rn(f0, f1);
        __half2 h1 = __floats2half2_rn(f2, f3);
        __half2 h2 = __floats2half2_rn(f4, f5);
        __half2 h3 = __floats2half2_rn(f6, f7);
        uint4 hv;
        hv.x = *(unsigned*)&h0; hv.y = *(unsigned*)&h1;
        hv.z = *(unsigned*)&h2; hv.w = *(unsigned*)&h3;
        *(uint4*)(sZ + node * FEAT + (l << 3)) = hv;
    }
    __syncthreads();

    // ---- MLP phase: 16 warps; 2 warps per node; each warp 2 o-tiles ----
    int w = t >> 5, lane = t & 31;
    int g = w >> 1, half = w & 1;
    int n = (blockIdx.x << 3) + g;
    uint32_t zbase = smem_u32(sZ + g * FEAT);
    int r = lane >> 2, q = lane & 3;

    // GEMM1
    unsigned bf[4][2];
#pragma unroll
    for (int k = 0; k < 4; k++)
        ldmBt(bf[k], zbase + ((k * 16 + (lane & 15)) * 8) * 2);
    uint32_t w1base = smem_u32(sW1);
    float acc[2][4];
#pragma unroll
    for (int j = 0; j < 2; j++) {
        int ot = half * 2 + j;
#pragma unroll
        for (int i = 0; i < 4; i++) acc[j][i] = 0.f;
#pragma unroll
        for (int k = 0; k < 4; k++) {
            unsigned af[4];
            ldmA(af, w1base + (((ot * 16 + (lane & 15)) * 64) + k * 16 + ((lane >> 4) << 3)) * 2);
            mma16816(acc[j], af, bf[k]);
        }
    }
    __syncthreads();   // all reads of z done before y overwrites tiles
    // epilogue 1: y = relu(acc + b1) -> own channels of node tile
#pragma unroll
    for (int j = 0; j < 2; j++) {
        int ot = half * 2 + j;
        int oa = ot * 16 + r, ob = oa + 8;
        float ba = sB1[oa], bb = sB1[ob];
        __half2 ya = __floats2half2_rn(fmaxf(acc[j][0] + ba, 0.f), fmaxf(acc[j][1] + ba, 0.f));
        __half2 yb = __floats2half2_rn(fmaxf(acc[j][2] + bb, 0.f), fmaxf(acc[j][3] + bb, 0.f));
        *(__half2*)(sZ + g * FEAT + oa * 8 + 2 * q) = ya;
        *(__half2*)(sZ + g * FEAT + ob * 8 + 2 * q) = yb;
    }
    __syncthreads();

    // GEMM2
#pragma unroll
    for (int k = 0; k < 4; k++)
        ldmBt(bf[k], zbase + ((k * 16 + (lane & 15)) * 8) * 2);
    uint32_t w2base = smem_u32(sW2);
#pragma unroll
    for (int j = 0; j < 2; j++) {
        int ot = half * 2 + j;
#pragma unroll
        for (int i = 0; i < 4; i++) acc[j][i] = 0.f;
#pragma unroll
        for (int k = 0; k < 4; k++) {
            unsigned af[4];
            ldmA(af, w2base + (((ot * 16 + (lane & 15)) * 64) + k * 16 + ((lane >> 4) << 3)) * 2);
            mma16816(acc[j], af, bf[k]);
        }
    }
    // epilogue 2: h = relu(acc + b2) -> global (pong buffer) + stats
    __half* hrow = outb + (size_t)n * FEAT;
#pragma unroll
    for (int j = 0; j < 2; j++) {
        int ot = half * 2 + j;
        int oa = ot * 16 + r, ob = oa + 8;
        float ba = sB2[oa], bb = sB2[ob];
        float f0 = fmaxf(acc[j][0] + ba, 0.f), f1 = fmaxf(acc[j][1] + ba, 0.f);
        float f2 = fmaxf(acc[j][2] + bb, 0.f), f3 = fmaxf(acc[j][3] + bb, 0.f);
        *(__half2*)(hrow + oa * 8 + 2 * q) = __floats2half2_rn(f0, f1);
        *(__half2*)(hrow + ob * 8 + 2 * q) = __floats2half2_rn(f2, f3);
        float sa = f0 + f1, qa = f0 * f0 + f1 * f1;
        float sb = f2 + f3, qb = f2 * f2 + f3 * f3;
        sa += __shfl_xor_sync(0xffffffffu, sa, 1); sa += __shfl_xor_sync(0xffffffffu, sa, 2);
        qa += __shfl_xor_sync(0xffffffffu, qa, 1); qa += __shfl_xor_sync(0xffffffffu, qa, 2);
        sb += __shfl_xor_sync(0xffffffffu, sb, 1); sb += __shfl_xor_sync(0xffffffffu, sb, 2);
        qb += __shfl_xor_sync(0xffffffffu, qb, 1); qb += __shfl_xor_sync(0xffffffffu, qb, 2);
        if (q == 0) {
            atomicAdd(&sStats[oa], sa);
            atomicAdd(&sStats[64 + oa], qa);
            atomicAdd(&sStats[ob], sb);
            atomicAdd(&sStats[64 + ob], qb);
        }
    }
    __syncthreads();
    if (t < 128) atomicAdd(&g_stats[layer * 128 + t], sStats[t]);
}

// ---------------- BN finalize: stats -> (scale, shift) ----------------
__global__ void k_finalize(int layer, const float* __restrict__ gamma,
                           const float* __restrict__ beta) {
    int c = threadIdx.x;  // 64 threads
    const float* st = g_stats + layer * 128;
    float inv = 1.0f / 160000.0f;
    float mean = st[c] * inv;
    float var = st[64 + c] * inv - mean * mean;
    float sc = gamma[c] * rsqrtf(var + 1e-5f);
    g_affine[layer * 128 + c]      = sc;
    g_affine[layer * 128 + 64 + c] = beta[c] - mean * sc;
}

// ---------------- pooling + head ----------------
__global__ void k_pool() {   // layer-4 output lands in g_hbuf (L4: h2 -> hbuf)
    int t = threadIdx.x;     // 256 threads; 2 consecutive elements each
    float a0 = 0.f, a1 = 0.f;
    for (int n = blockIdx.x; n < N_NODES; n += gridDim.x) {
        __half2 v = *(const __half2*)(g_hbuf + (size_t)n * FEAT + t * 2);
        float2 p = __half22float2(v);
        a0 += p.x; a1 += p.y;
    }
    atomicAdd(&g_pool[t * 2], a0);
    atomicAdd(&g_pool[t * 2 + 1], a1);
}

__global__ void k_final(const float* __restrict__ wout,
                        const float* __restrict__ bout, float* __restrict__ o) {
    int m = threadIdx.x;
    if (m < 8) {
        const float* aff = g_affine + 4 * 128;
        float acc = bout[0];
        for (int c = 0; c < 64; c++)
            acc += wout[c] * (aff[c] * g_pool[c * 8 + m] * (1.0f / N_NODES) + aff[64 + c]);
        o[m] = 1.0f / (1.0f + expf(-acc));
    }
}

// ---------------- launch ----------------
extern "C" void kernel_launch(void* const* d_in, const int* in_sizes, int n_in,
                              void* d_out, int out_size) {
    const float* x     = (const float*)d_in[0];
    const void*  ei    = d_in[1];
    // d_in[2] = batch (unused, all zeros)
    const float* w10   = (const float*)d_in[3];
    const float* w1    = (const float*)d_in[4];
    const float* b1    = (const float*)d_in[5];
    const float* w2    = (const float*)d_in[6];
    const float* b2    = (const float*)d_in[7];
    const float* gamma = (const float*)d_in[8];
    const float* beta  = (const float*)d_in[9];
    const float* wout  = (const float*)d_in[10];
    const float* bout  = (const float*)d_in[11];
    float* out = (float*)d_out;

    k_init<<<(N_NODES + 255) / 256, 256>>>(ei);
    k_prep<<<(9 * 4096 + 255) / 256, 256>>>(w1, w2);
    k_hist<<<(N_EDGES + 255) / 256, 256>>>(ei);
    k_scan<<<1, 1024>>>();
    k_fill<<<(N_EDGES + 255) / 256, 256>>>(ei);

    k_layer0<<<N_NODES / 8, 128>>>(x, w10, b1, b2);
    k_finalize<<<1, 64>>>(0, gamma, beta);
    for (int i = 1; i <= 4; i++) {
        k_layer<<<N_NODES / 8, 512>>>(i, b1 + i * 64, b2 + i * 64);
        k_finalize<<<1, 64>>>(i, gamma + i * 64, beta + i * 64);
    }
    k_pool<<<256, 256>>>();
    k_final<<<1, 32>>>(wout, bout, out);
}

// round 10
// speedup vs baseline: 1.1065x; 1.1065x over previous
#include <cuda_runtime.h>
#include <cuda_fp16.h>
#include <cstdint>

// GIN: 5 layers, N=20000 nodes, E=320000 edges, HIDDEN=64, M=8.
//  - CSR build per launch (histogram + scan + fill).
//  - h/z fp16, L2-resident. k_gather: fp16 CSR gather (8-edge unrolled) +
//    BN affine -> z fp16. k_mlp: HMMA (m16n8k16) GEMM pair, [c][m]-invariant.
//  - BN folded to per-channel affine; finalize kernel per layer.
//  - Split gather/MLP kernels: gather warps retire independently (no block
//    barrier behind max-degree nodes); MLP is tensor-pipe bound.

#define N_NODES 20000
#define N_EDGES 320000
#define HID 64
#define MDIM 8
#define FEAT (HID*MDIM)   // 512 elements per node

typedef unsigned long long ull;

// ---------------- device scratch ----------------
__device__ __half g_hbuf[N_NODES * FEAT];   // h fp16 (gather + pool source)
__device__ __half g_z16[N_NODES * FEAT];    // z fp16 scratch
__device__ int    g_rowptr[N_NODES + 1];
__device__ int    g_count[N_NODES];
__device__ int    g_fill[N_NODES];
__device__ int    g_srce[N_EDGES];
__device__ float  g_stats[5 * 128];         // per layer: sum[64], sumsq[64]
__device__ float  g_affine[5 * 128];        // per layer: scale[64], shift[64]
__device__ ull    g_Wt2p[4096];             // W2 layer 0 (layer0 FFMA2 path), [c][o] pairs
__device__ __half g_W1h[4 * 4096];          // W1 layers 1..4, [o][c] fp16
__device__ __half g_W2h[5 * 4096];          // W2 layers 0..4, [o][c] fp16
__device__ float  g_pool[FEAT];
__device__ int    g_is64;

// ---------------- helpers ----------------
__device__ __forceinline__ ull pk2(float a, float b) {
    ull r; asm("mov.b64 %0, {%1, %2};" : "=l"(r) : "f"(a), "f"(b)); return r;
}
__device__ __forceinline__ float2 upk(ull v) {
    float2 r; asm("mov.b64 {%0, %1}, %2;" : "=f"(r.x), "=f"(r.y) : "l"(v)); return r;
}
__device__ __forceinline__ void fma2(ull& a, ull b, ull c) {
    asm("fma.rn.f32x2 %0, %1, %2, %0;" : "+l"(a) : "l"(b), "l"(c));
}
__device__ __forceinline__ uint32_t smem_u32(const void* p) {
    return (uint32_t)__cvta_generic_to_shared(p);
}
__device__ __forceinline__ void ldmA(unsigned a[4], uint32_t addr) {
    asm volatile("ldmatrix.sync.aligned.m8n8.x4.shared.b16 {%0,%1,%2,%3}, [%4];"
        : "=r"(a[0]), "=r"(a[1]), "=r"(a[2]), "=r"(a[3]) : "r"(addr));
}
__device__ __forceinline__ void ldmBt(unsigned b[2], uint32_t addr) {
    asm volatile("ldmatrix.sync.aligned.m8n8.x2.trans.shared.b16 {%0,%1}, [%2];"
        : "=r"(b[0]), "=r"(b[1]) : "r"(addr));
}
__device__ __forceinline__ void mma16816(float d[4], const unsigned a[4], const unsigned b[2]) {
    asm volatile("mma.sync.aligned.m16n8k16.row.col.f32.f16.f16.f32 "
        "{%0,%1,%2,%3}, {%4,%5,%6,%7}, {%8,%9}, {%0,%1,%2,%3};"
        : "+f"(d[0]), "+f"(d[1]), "+f"(d[2]), "+f"(d[3])
        : "r"(a[0]), "r"(a[1]), "r"(a[2]), "r"(a[3]), "r"(b[0]), "r"(b[1]));
}

// ---------------- setup kernels ----------------
__global__ void k_init(const void* ei) {
    __shared__ int s_ok;
    if (threadIdx.x == 0) s_ok = 1;
    __syncthreads();
    int i = blockIdx.x * blockDim.x + threadIdx.x;
    if (i < N_NODES) { g_count[i] = 0; g_fill[i] = 0; }
    if (i < 5 * 128) g_stats[i] = 0.f;
    if (i < FEAT)    g_pool[i] = 0.f;
    // dtype detect: first 64 values as u64; any >= N_NODES => int32 layout
    if (blockIdx.x == 0 && threadIdx.x < 64) {
        if (((const ull*)ei)[threadIdx.x] >= (ull)N_NODES) atomicExch(&s_ok, 0);
    }
    __syncthreads();
    if (blockIdx.x == 0 && threadIdx.x == 0) g_is64 = s_ok;
}

__device__ __forceinline__ int edge_at(const void* ei, int idx) {
    return g_is64 ? (int)((const long long*)ei)[idx] : ((const int*)ei)[idx];
}

__global__ void k_hist(const void* ei) {
    int e = blockIdx.x * blockDim.x + threadIdx.x;
    if (e >= N_EDGES) return;
    atomicAdd(&g_count[edge_at(ei, N_EDGES + e)], 1);
}

__global__ void k_scan() {   // 1 block, 1024 threads, exclusive prefix over 20000
    __shared__ int s[1024];
    const int CH = 20;       // 5 x int4 per thread
    int t = threadIdx.x;
    int base = t * CH;
    int raw[CH];
    // vectorized loads: g_count is int4-aligned; 20000 = 1000 threads x 20
    if (base + CH <= N_NODES) {
#pragma unroll
        for (int v4 = 0; v4 < 5; v4++) {
            int4 v = *(const int4*)(g_count + base + v4 * 4);
            raw[v4 * 4 + 0] = v.x; raw[v4 * 4 + 1] = v.y;
            raw[v4 * 4 + 2] = v.z; raw[v4 * 4 + 3] = v.w;
        }
    } else {
#pragma unroll
        for (int j = 0; j < CH; j++)
            raw[j] = (base + j < N_NODES) ? g_count[base + j] : 0;
    }
    int vals[CH];
    int local = 0;
#pragma unroll
    for (int j = 0; j < CH; j++) { vals[j] = local; local += raw[j]; }
    s[t] = local;
    __syncthreads();
    for (int off = 1; off < 1024; off <<= 1) {
        int v = s[t];
        int add = (t >= off) ? s[t - off] : 0;
        __syncthreads();
        s[t] = v + add;
        __syncthreads();
    }
    int bb = (t == 0) ? 0 : s[t - 1];
#pragma unroll
    for (int j = 0; j < CH; j++) {
        int i = base + j;
        if (i < N_NODES) g_rowptr[i] = bb + vals[j];
    }
    if (t == 1023) g_rowptr[N_NODES] = s[1023];
}

__global__ void k_fill(const void* ei) {
    int e = blockIdx.x * blockDim.x + threadIdx.x;
    if (e >= N_EDGES) return;
    int srcv = edge_at(ei, e);
    int d    = edge_at(ei, N_EDGES + e);
    int pos  = g_rowptr[d] + atomicAdd(&g_fill[d], 1);
    g_srce[pos] = srcv;
}

// weight prep: fp16 copies of W1 (1..4) / W2 (0..4) [o][c]; fp32 pairs for layer0 W2.
__global__ void k_prep(const float* __restrict__ w1, const float* __restrict__ w2) {
    int idx = blockIdx.x * blockDim.x + threadIdx.x;
    if (idx < 4 * 4096) {
        g_W1h[idx] = __float2half(w1[idx]);
    } else if (idx < 9 * 4096) {
        int j = idx - 4 * 4096;
        float v = w2[j];
        g_W2h[j] = __float2half(v);
        if (j < 4096) {
            int o = j >> 6, c = j & 63;
            g_Wt2p[(c << 6) + o] = pk2(v, v);
        }
    }
}

// ---------------- layer0 FFMA2 GEMM core (once per launch) ----------------
__device__ __forceinline__ void gemm64(const float* sIn, const ull* __restrict__ Wp,
                                       ull acc[16]) {
#pragma unroll
    for (int i = 0; i < 16; i++) acc[i] = 0ULL;
#pragma unroll 8
    for (int c = 0; c < 64; c++) {
        ulonglong2 wa = *(const ulonglong2*)(Wp + (c << 6));
        ulonglong2 wb = *(const ulonglong2*)(Wp + (c << 6) + 2);
        ulonglong2 za = *(const ulonglong2*)(sIn + (c << 3));
        ulonglong2 zb = *(const ulonglong2*)(sIn + (c << 3) + 4);
        ull w0 = wa.x, w1 = wa.y, w2 = wb.x, w3 = wb.y;
        ull z0 = za.x, z1 = za.y, z2 = zb.x, z3 = zb.y;
        fma2(acc[0],  w0, z0); fma2(acc[1],  w0, z1); fma2(acc[2],  w0, z2); fma2(acc[3],  w0, z3);
        fma2(acc[4],  w1, z0); fma2(acc[5],  w1, z1); fma2(acc[6],  w1, z2); fma2(acc[7],  w1, z3);
        fma2(acc[8],  w2, z0); fma2(acc[9],  w2, z1); fma2(acc[10], w2, z2); fma2(acc[11], w2, z3);
        fma2(acc[12], w3, z0); fma2(acc[13], w3, z1); fma2(acc[14], w3, z2); fma2(acc[15], w3, z3);
    }
}

__device__ __forceinline__ void epi2_l0(const ull acc[16], const float* sB2,
                                        __half* outh, int o0, float* sStats) {
#pragma unroll
    for (int r = 0; r < 4; r++) {
        int o = o0 + r;
        float b = sB2[o];
        float2 p0 = upk(acc[r * 4 + 0]), p1 = upk(acc[r * 4 + 1]);
        float2 p2 = upk(acc[r * 4 + 2]), p3 = upk(acc[r * 4 + 3]);
        float f0 = fmaxf(p0.x + b, 0.f), f1 = fmaxf(p0.y + b, 0.f);
        float f2 = fmaxf(p1.x + b, 0.f), f3 = fmaxf(p1.y + b, 0.f);
        float f4 = fmaxf(p2.x + b, 0.f), f5 = fmaxf(p2.y + b, 0.f);
        float f6 = fmaxf(p3.x + b, 0.f), f7 = fmaxf(p3.y + b, 0.f);
        __half2 h0 = __floats2half2_rn(f0, f1);
        __half2 h1 = __floats2half2_rn(f2, f3);
        __half2 h2 = __floats2half2_rn(f4, f5);
        __half2 h3 = __floats2half2_rn(f6, f7);
        uint4 hv;
        hv.x = *(unsigned*)&h0; hv.y = *(unsigned*)&h1;
        hv.z = *(unsigned*)&h2; hv.w = *(unsigned*)&h3;
        *(uint4*)(outh + o * 8) = hv;
        float s = f0 + f1 + f2 + f3 + f4 + f5 + f6 + f7;
        float q = f0*f0 + f1*f1 + f2*f2 + f3*f3 + f4*f4 + f5*f5 + f6*f6 + f7*f7;
        s += __shfl_xor_sync(0xffffffffu, s, 16);
        q += __shfl_xor_sync(0xffffffffu, q, 16);
        if ((threadIdx.x & 16) == 0) {
            atomicAdd(&sStats[o], s);
            atomicAdd(&sStats[64 + o], q);
        }
    }
}

// ---------------- layer 0 (IN_DIM=1) ----------------
__global__ void __launch_bounds__(128) k_layer0(
    const float* __restrict__ x, const float* __restrict__ w10,
    const float* __restrict__ b1, const float* __restrict__ b2) {
    __shared__ float sZ[8 * FEAT];
    __shared__ float sZ0[64];
    __shared__ float sStats[128];
    __shared__ float sB2[64];
    int t = threadIdx.x;
    sStats[t] = 0.f;
    if (t < 64) sB2[t] = b2[t];
    int g = t >> 4, l = t & 15;
    int n = (blockIdx.x << 3) + g;
    if (l < 8) {
        float a = x[n * 8 + l];
        int rs = g_rowptr[n], re = g_rowptr[n + 1];
        for (int e = rs; e < re; e++) a += x[g_srce[e] * 8 + l];
        sZ0[g * 8 + l] = a;
    }
    __syncthreads();
    int o0 = l << 2;
    float zz[8];
#pragma unroll
    for (int m = 0; m < 8; m++) zz[m] = sZ0[g * 8 + m];
#pragma unroll
    for (int r = 0; r < 4; r++) {
        int o = o0 + r;
        float w = w10[o], b = b1[o];
        float4 v0, v1;
        v0.x = fmaxf(w * zz[0] + b, 0.f); v0.y = fmaxf(w * zz[1] + b, 0.f);
        v0.z = fmaxf(w * zz[2] + b, 0.f); v0.w = fmaxf(w * zz[3] + b, 0.f);
        v1.x = fmaxf(w * zz[4] + b, 0.f); v1.y = fmaxf(w * zz[5] + b, 0.f);
        v1.z = fmaxf(w * zz[6] + b, 0.f); v1.w = fmaxf(w * zz[7] + b, 0.f);
        *(float4*)(sZ + (g << 9) + o * 8)     = v0;
        *(float4*)(sZ + (g << 9) + o * 8 + 4) = v1;
    }
    __syncthreads();
    ull acc[16];
    gemm64(sZ + (g << 9), g_Wt2p + o0, acc);
    epi2_l0(acc, sB2, g_hbuf + (size_t)n * FEAT, o0, sStats);
    __syncthreads();
    atomicAdd(&g_stats[t], sStats[t]);
}

// ---------------- gather (layers 1..4): fp16 CSR gather + BN affine -> z fp16 ----
// 64 threads per node, one channel per thread; 8 edges in flight.
__device__ __forceinline__ void acc8(float a[8], uint4 v) {
    float2 p;
    p = __half22float2(*(const __half2*)&v.x); a[0] += p.x; a[1] += p.y;
    p = __half22float2(*(const __half2*)&v.y); a[2] += p.x; a[3] += p.y;
    p = __half22float2(*(const __half2*)&v.z); a[4] += p.x; a[5] += p.y;
    p = __half22float2(*(const __half2*)&v.w); a[6] += p.x; a[7] += p.y;
}

__global__ void __launch_bounds__(256) k_gather(int layer) {
    const uint4* __restrict__ in = (const uint4*)g_hbuf;  // 64 uint4 per node row
    int t = threadIdx.x;
    int grp = t >> 6;          // node within block: 0..3
    int l = t & 63;            // channel
    int n = (blockIdx.x << 2) + grp;
    int rs = g_rowptr[n], re = g_rowptr[n + 1];
    float sc = g_affine[(layer - 1) * 128 + l];
    float sh = g_affine[(layer - 1) * 128 + 64 + l];
    float a[8] = {0,0,0,0,0,0,0,0}, b[8] = {0,0,0,0,0,0,0,0};
    acc8(a, in[(size_t)n * 64 + l]);   // self
    int e = rs;
    for (; e + 8 <= re; e += 8) {
        uint4 v0 = in[(size_t)g_srce[e]     * 64 + l];
        uint4 v1 = in[(size_t)g_srce[e + 1] * 64 + l];
        uint4 v2 = in[(size_t)g_srce[e + 2] * 64 + l];
        uint4 v3 = in[(size_t)g_srce[e + 3] * 64 + l];
        uint4 v4 = in[(size_t)g_srce[e + 4] * 64 + l];
        uint4 v5 = in[(size_t)g_srce[e + 5] * 64 + l];
        uint4 v6 = in[(size_t)g_srce[e + 6] * 64 + l];
        uint4 v7 = in[(size_t)g_srce[e + 7] * 64 + l];
        acc8(a, v0); acc8(b, v1); acc8(a, v2); acc8(b, v3);
        acc8(a, v4); acc8(b, v5); acc8(a, v6); acc8(b, v7);
    }
    if (e + 4 <= re) {
        uint4 v0 = in[(size_t)g_srce[e]     * 64 + l];
        uint4 v1 = in[(size_t)g_srce[e + 1] * 64 + l];
        uint4 v2 = in[(size_t)g_srce[e + 2] * 64 + l];
        uint4 v3 = in[(size_t)g_srce[e + 3] * 64 + l];
        acc8(a, v0); acc8(b, v1); acc8(a, v2); acc8(b, v3);
        e += 4;
    }
    for (; e < re; e++) acc8(a, in[(size_t)g_srce[e] * 64 + l]);
    float shd = sh * (float)(re - rs + 1);
    float f0 = sc * (a[0] + b[0]) + shd, f1 = sc * (a[1] + b[1]) + shd;
    float f2 = sc * (a[2] + b[2]) + shd, f3 = sc * (a[3] + b[3]) + shd;
    float f4 = sc * (a[4] + b[4]) + shd, f5 = sc * (a[5] + b[5]) + shd;
    float f6 = sc * (a[6] + b[6]) + shd, f7 = sc * (a[7] + b[7]) + shd;
    __half2 h0 = __floats2half2_rn(f0, f1);
    __half2 h1 = __floats2half2_rn(f2, f3);
    __half2 h2 = __floats2half2_rn(f4, f5);
    __half2 h3 = __floats2half2_rn(f6, f7);
    uint4 hv;
    hv.x = *(unsigned*)&h0; hv.y = *(unsigned*)&h1;
    hv.z = *(unsigned*)&h2; hv.w = *(unsigned*)&h3;
    *(uint4*)(g_z16 + (size_t)n * FEAT + (l << 3)) = hv;
}

// ---------------- MLP (layers 1..4): tensor-core GEMM pair ----------------
// 256 threads = 8 warps, 1 node per warp, 8 nodes per block.
__global__ void __launch_bounds__(256) k_mlp(
    int layer, const float* __restrict__ b1, const float* __restrict__ b2) {
    __shared__ __half sW1[4096];
    __shared__ __half sW2[4096];
    __shared__ __half sZ[8 * FEAT];   // 8 node tiles [c64][m8], reused z -> y
    __shared__ float sStats[128];
    __shared__ float sB1[64], sB2[64];
    int t = threadIdx.x;
    int w = t >> 5, lane = t & 31;
    if (t < 128) sStats[t] = 0.f;
    if (t < 64) { sB1[t] = b1[t]; sB2[t] = b2[t]; }
    const uint4* w1src = (const uint4*)(g_W1h + (size_t)(layer - 1) * 4096);
    const uint4* w2src = (const uint4*)(g_W2h + (size_t)layer * 4096);
    const uint4* zsrc  = (const uint4*)(g_z16 + (size_t)(blockIdx.x << 3) * FEAT);
    ((uint4*)sW1)[t] = w1src[t];  ((uint4*)sW1)[t + 256] = w1src[t + 256];
    ((uint4*)sW2)[t] = w2src[t];  ((uint4*)sW2)[t + 256] = w2src[t + 256];
    ((uint4*)sZ)[t]  = zsrc[t];   ((uint4*)sZ)[t + 256]  = zsrc[t + 256];
    __syncthreads();

    int n = (blockIdx.x << 3) + w;
    uint32_t zbase = smem_u32(sZ + w * FEAT);
    int r = lane >> 2, q = lane & 3;

    // ---- GEMM1 ----
    unsigned bf[4][2];
#pragma unroll
    for (int k = 0; k < 4; k++)
        ldmBt(bf[k], zbase + ((k * 16 + (lane & 15)) * 8) * 2);
    uint32_t w1base = smem_u32(sW1);
    float acc[4][4];
#pragma unroll
    for (int ot = 0; ot < 4; ot++) {
#pragma unroll
        for (int i = 0; i < 4; i++) acc[ot][i] = 0.f;
#pragma unroll
        for (int k = 0; k < 4; k++) {
            unsigned af[4];
            ldmA(af, w1base + (((ot * 16 + (lane & 15)) * 64) + k * 16 + ((lane >> 4) << 3)) * 2);
            mma16816(acc[ot], af, bf[k]);
        }
    }
    // epilogue 1: y = relu(acc + b1) -> overwrite own z tile (warp-private)
#pragma unroll
    for (int ot = 0; ot < 4; ot++) {
        int oa = ot * 16 + r, ob = oa + 8;
        float ba = sB1[oa], bb = sB1[ob];
        __half2 ya = __floats2half2_rn(fmaxf(acc[ot][0] + ba, 0.f), fmaxf(acc[ot][1] + ba, 0.f));
        __half2 yb = __floats2half2_rn(fmaxf(acc[ot][2] + bb, 0.f), fmaxf(acc[ot][3] + bb, 0.f));
        *(__half2*)(sZ + w * FEAT + oa * 8 + 2 * q) = ya;
        *(__half2*)(sZ + w * FEAT + ob * 8 + 2 * q) = yb;
    }
    __syncwarp();

    // ---- GEMM2 ----
#pragma unroll
    for (int k = 0; k < 4; k++)
        ldmBt(bf[k], zbase + ((k * 16 + (lane & 15)) * 8) * 2);
    uint32_t w2base = smem_u32(sW2);
#pragma unroll
    for (int ot = 0; ot < 4; ot++) {
#pragma unroll
        for (int i = 0; i < 4; i++) acc[ot][i] = 0.f;
#pragma unroll
        for (int k = 0; k < 4; k++) {
            unsigned af[4];
            ldmA(af, w2base + (((ot * 16 + (lane & 15)) * 64) + k * 16 + ((lane >> 4) << 3)) * 2);
            mma16816(acc[ot], af, bf[k]);
        }
    }
    // epilogue 2: h = relu(acc + b2) -> global fp16 + stats
    __half* hrow = g_hbuf + (size_t)n * FEAT;
#pragma unroll
    for (int ot = 0; ot < 4; ot++) {
        int oa = ot * 16 + r, ob = oa + 8;
        float ba = sB2[oa], bb = sB2[ob];
        float f0 = fmaxf(acc[ot][0] + ba, 0.f), f1 = fmaxf(acc[ot][1] + ba, 0.f);
        float f2 = fmaxf(acc[ot][2] + bb, 0.f), f3 = fmaxf(acc[ot][3] + bb, 0.f);
        *(__half2*)(hrow + oa * 8 + 2 * q) = __floats2half2_rn(f0, f1);
        *(__half2*)(hrow + ob * 8 + 2 * q) = __floats2half2_rn(f2, f3);
        float sa = f0 + f1, qa = f0 * f0 + f1 * f1;
        float sb = f2 + f3, qb = f2 * f2 + f3 * f3;
        sa += __shfl_xor_sync(0xffffffffu, sa, 1); sa += __shfl_xor_sync(0xffffffffu, sa, 2);
        qa += __shfl_xor_sync(0xffffffffu, qa, 1); qa += __shfl_xor_sync(0xffffffffu, qa, 2);
        sb += __shfl_xor_sync(0xffffffffu, sb, 1); sb += __shfl_xor_sync(0xffffffffu, sb, 2);
        qb += __shfl_xor_sync(0xffffffffu, qb, 1); qb += __shfl_xor_sync(0xffffffffu, qb, 2);
        if (q == 0) {
            atomicAdd(&sStats[oa], sa);
            atomicAdd(&sStats[64 + oa], qa);
            atomicAdd(&sStats[ob], sb);
            atomicAdd(&sStats[64 + ob], qb);
        }
    }
    __syncthreads();
    if (t < 128) atomicAdd(&g_stats[layer * 128 + t], sStats[t]);
}

// ---------------- BN finalize: stats -> (scale, shift) ----------------
__global__ void k_finalize(int layer, const float* __restrict__ gamma,
                           const float* __restrict__ beta) {
    int c = threadIdx.x;  // 64 threads
    const float* st = g_stats + layer * 128;
    float inv = 1.0f / 160000.0f;
    float mean = st[c] * inv;
    float var = st[64 + c] * inv - mean * mean;
    float sc = gamma[c] * rsqrtf(var + 1e-5f);
    g_affine[layer * 128 + c]      = sc;
    g_affine[layer * 128 + 64 + c] = beta[c] - mean * sc;
}

// ---------------- pooling + head ----------------
__global__ void k_pool() {   // reads raw layer-4 fp16 output in g_hbuf
    int t = threadIdx.x;     // 256 threads; 2 consecutive elements each
    float a0 = 0.f, a1 = 0.f;
    for (int n = blockIdx.x; n < N_NODES; n += gridDim.x) {
        __half2 v = *(const __half2*)(g_hbuf + (size_t)n * FEAT + t * 2);
        float2 p = __half22float2(v);
        a0 += p.x; a1 += p.y;
    }
    atomicAdd(&g_pool[t * 2], a0);
    atomicAdd(&g_pool[t * 2 + 1], a1);
}

__global__ void k_final(const float* __restrict__ wout,
                        const float* __restrict__ bout, float* __restrict__ o) {
    int m = threadIdx.x;
    if (m < 8) {
        const float* aff = g_affine + 4 * 128;
        float acc = bout[0];
        for (int c = 0; c < 64; c++)
            acc += wout[c] * (aff[c] * g_pool[c * 8 + m] * (1.0f / N_NODES) + aff[64 + c]);
        o[m] = 1.0f / (1.0f + expf(-acc));
    }
}

// ---------------- launch ----------------
extern "C" void kernel_launch(void* const* d_in, const int* in_sizes, int n_in,
                              void* d_out, int out_size) {
    const float* x     = (const float*)d_in[0];
    const void*  ei    = d_in[1];
    // d_in[2] = batch (unused, all zeros)
    const float* w10   = (const float*)d_in[3];
    const float* w1    = (const float*)d_in[4];
    const float* b1    = (const float*)d_in[5];
    const float* w2    = (const float*)d_in[6];
    const float* b2    = (const float*)d_in[7];
    const float* gamma = (const float*)d_in[8];
    const float* beta  = (const float*)d_in[9];
    const float* wout  = (const float*)d_in[10];
    const float* bout  = (const float*)d_in[11];
    float* out = (float*)d_out;

    k_init<<<(N_NODES + 255) / 256, 256>>>(ei);
    k_prep<<<(9 * 4096 + 255) / 256, 256>>>(w1, w2);
    k_hist<<<(N_EDGES + 255) / 256, 256>>>(ei);
    k_scan<<<1, 1024>>>();
    k_fill<<<(N_EDGES + 255) / 256, 256>>>(ei);

    k_layer0<<<N_NODES / 8, 128>>>(x, w10, b1, b2);
    k_finalize<<<1, 64>>>(0, gamma, beta);
    for (int i = 1; i <= 4; i++) {
        k_gather<<<N_NODES / 4, 256>>>(i);
        k_mlp<<<N_NODES / 8, 256>>>(i, b1 + i * 64, b2 + i * 64);
        k_finalize<<<1, 64>>>(i, gamma + i * 64, beta + i * 64);
    }
    k_pool<<<256, 256>>>();
    k_final<<<1, 32>>>(wout, bout, out);
}

// round 12
// speedup vs baseline: 1.9162x; 1.7317x over previous
#include <cuda_runtime.h>
#include <cuda_fp16.h>
#include <cstdint>

// GIN: 5 layers, N=20000 nodes, E=320000 edges, HIDDEN=64, M=8.
//  - CSR build per launch (histogram + scan + fill).
//  - h/z fp16, L2-resident. k_gather: fp16 CSR gather + local BN-affine
//    (computed per block from g_stats) -> z fp16.
//  - k_mlp: HMMA (m16n8k16) GEMM pair; weights staged in smem with rows
//    padded to 144B (72 halves) so ldmatrix row-pointers are bank-conflict-free.
//  - No separate finalize kernels; k_final folds layer-4 BN into the head.

#define N_NODES 20000
#define N_EDGES 320000
#define HID 64
#define MDIM 8
#define FEAT (HID*MDIM)   // 512 elements per node
#define WPAD 72           // padded halves per weight row (144B, 9 uint4)

typedef unsigned long long ull;

// ---------------- device scratch ----------------
__device__ __half g_hbuf[N_NODES * FEAT];   // h fp16 (gather + pool source)
__device__ __half g_z16[N_NODES * FEAT];    // z fp16 scratch
__device__ int    g_rowptr[N_NODES + 1];
__device__ int    g_count[N_NODES];
__device__ int    g_fill[N_NODES];
__device__ int    g_srce[N_EDGES];
__device__ float  g_stats[5 * 128];         // per layer: sum[64], sumsq[64]
__device__ ull    g_Wt2p[4096];             // W2 layer 0 (layer0 FFMA2 path), [c][o] pairs
__device__ __half g_W1h[4 * 4096];          // W1 layers 1..4, [o][c] fp16
__device__ __half g_W2h[5 * 4096];          // W2 layers 0..4, [o][c] fp16
__device__ float  g_pool[FEAT];
__device__ int    g_is64;

// ---------------- helpers ----------------
__device__ __forceinline__ ull pk2(float a, float b) {
    ull r; asm("mov.b64 %0, {%1, %2};" : "=l"(r) : "f"(a), "f"(b)); return r;
}
__device__ __forceinline__ float2 upk(ull v) {
    float2 r; asm("mov.b64 {%0, %1}, %2;" : "=f"(r.x), "=f"(r.y) : "l"(v)); return r;
}
__device__ __forceinline__ void fma2(ull& a, ull b, ull c) {
    asm("fma.rn.f32x2 %0, %1, %2, %0;" : "+l"(a) : "l"(b), "l"(c));
}
__device__ __forceinline__ uint32_t smem_u32(const void* p) {
    return (uint32_t)__cvta_generic_to_shared(p);
}
__device__ __forceinline__ void ldmA(unsigned a[4], uint32_t addr) {
    asm volatile("ldmatrix.sync.aligned.m8n8.x4.shared.b16 {%0,%1,%2,%3}, [%4];"
        : "=r"(a[0]), "=r"(a[1]), "=r"(a[2]), "=r"(a[3]) : "r"(addr));
}
__device__ __forceinline__ void ldmBt(unsigned b[2], uint32_t addr) {
    asm volatile("ldmatrix.sync.aligned.m8n8.x2.trans.shared.b16 {%0,%1}, [%2];"
        : "=r"(b[0]), "=r"(b[1]) : "r"(addr));
}
__device__ __forceinline__ void mma16816(float d[4], const unsigned a[4], const unsigned b[2]) {
    asm volatile("mma.sync.aligned.m16n8k16.row.col.f32.f16.f16.f32 "
        "{%0,%1,%2,%3}, {%4,%5,%6,%7}, {%8,%9}, {%0,%1,%2,%3};"
        : "+f"(d[0]), "+f"(d[1]), "+f"(d[2]), "+f"(d[3])
        : "r"(a[0]), "r"(a[1]), "r"(a[2]), "r"(a[3]), "r"(b[0]), "r"(b[1]));
}

// ---------------- setup kernels ----------------
__global__ void k_init(const void* ei) {
    __shared__ int s_ok;
    if (threadIdx.x == 0) s_ok = 1;
    __syncthreads();
    int i = blockIdx.x * blockDim.x + threadIdx.x;
    if (i < N_NODES) { g_count[i] = 0; g_fill[i] = 0; }
    if (i < 5 * 128) g_stats[i] = 0.f;
    if (i < FEAT)    g_pool[i] = 0.f;
    if (blockIdx.x == 0 && threadIdx.x < 64) {
        if (((const ull*)ei)[threadIdx.x] >= (ull)N_NODES) atomicExch(&s_ok, 0);
    }
    __syncthreads();
    if (blockIdx.x == 0 && threadIdx.x == 0) g_is64 = s_ok;
}

__device__ __forceinline__ int edge_at(const void* ei, int idx) {
    return g_is64 ? (int)((const long long*)ei)[idx] : ((const int*)ei)[idx];
}

__global__ void k_hist(const void* ei) {
    int e = blockIdx.x * blockDim.x + threadIdx.x;
    if (e >= N_EDGES) return;
    atomicAdd(&g_count[edge_at(ei, N_EDGES + e)], 1);
}

__global__ void k_scan() {   // 1 block, 1024 threads, exclusive prefix over 20000
    __shared__ int s[1024];
    const int CH = 20;
    int t = threadIdx.x;
    int base = t * CH;
    int raw[CH];
    if (base + CH <= N_NODES) {
#pragma unroll
        for (int v4 = 0; v4 < 5; v4++) {
            int4 v = *(const int4*)(g_count + base + v4 * 4);
            raw[v4 * 4 + 0] = v.x; raw[v4 * 4 + 1] = v.y;
            raw[v4 * 4 + 2] = v.z; raw[v4 * 4 + 3] = v.w;
        }
    } else {
#pragma unroll
        for (int j = 0; j < CH; j++)
            raw[j] = (base + j < N_NODES) ? g_count[base + j] : 0;
    }
    int vals[CH];
    int local = 0;
#pragma unroll
    for (int j = 0; j < CH; j++) { vals[j] = local; local += raw[j]; }
    s[t] = local;
    __syncthreads();
    for (int off = 1; off < 1024; off <<= 1) {
        int v = s[t];
        int add = (t >= off) ? s[t - off] : 0;
        __syncthreads();
        s[t] = v + add;
        __syncthreads();
    }
    int bb = (t == 0) ? 0 : s[t - 1];
#pragma unroll
    for (int j = 0; j < CH; j++) {
        int i = base + j;
        if (i < N_NODES) g_rowptr[i] = bb + vals[j];
    }
    if (t == 1023) g_rowptr[N_NODES] = s[1023];
}

__global__ void k_fill(const void* ei) {
    int e = blockIdx.x * blockDim.x + threadIdx.x;
    if (e >= N_EDGES) return;
    int srcv = edge_at(ei, e);
    int d    = edge_at(ei, N_EDGES + e);
    int pos  = g_rowptr[d] + atomicAdd(&g_fill[d], 1);
    g_srce[pos] = srcv;
}

// weight prep: fp16 copies of W1 (1..4) / W2 (0..4) [o][c]; fp32 pairs for layer0 W2.
__global__ void k_prep(const float* __restrict__ w1, const float* __restrict__ w2) {
    int idx = blockIdx.x * blockDim.x + threadIdx.x;
    if (idx < 4 * 4096) {
        g_W1h[idx] = __float2half(w1[idx]);
    } else if (idx < 9 * 4096) {
        int j = idx - 4 * 4096;
        float v = w2[j];
        g_W2h[j] = __float2half(v);
        if (j < 4096) {
            int o = j >> 6, c = j & 63;
            g_Wt2p[(c << 6) + o] = pk2(v, v);
        }
    }
}

// ---------------- layer0 FFMA2 GEMM core (once per launch) ----------------
__device__ __forceinline__ void gemm64(const float* sIn, const ull* __restrict__ Wp,
                                       ull acc[16]) {
#pragma unroll
    for (int i = 0; i < 16; i++) acc[i] = 0ULL;
#pragma unroll 8
    for (int c = 0; c < 64; c++) {
        ulonglong2 wa = *(const ulonglong2*)(Wp + (c << 6));
        ulonglong2 wb = *(const ulonglong2*)(Wp + (c << 6) + 2);
        ulonglong2 za = *(const ulonglong2*)(sIn + (c << 3));
        ulonglong2 zb = *(const ulonglong2*)(sIn + (c << 3) + 4);
        ull w0 = wa.x, w1 = wa.y, w2 = wb.x, w3 = wb.y;
        ull z0 = za.x, z1 = za.y, z2 = zb.x, z3 = zb.y;
        fma2(acc[0],  w0, z0); fma2(acc[1],  w0, z1); fma2(acc[2],  w0, z2); fma2(acc[3],  w0, z3);
        fma2(acc[4],  w1, z0); fma2(acc[5],  w1, z1); fma2(acc[6],  w1, z2); fma2(acc[7],  w1, z3);
        fma2(acc[8],  w2, z0); fma2(acc[9],  w2, z1); fma2(acc[10], w2, z2); fma2(acc[11], w2, z3);
        fma2(acc[12], w3, z0); fma2(acc[13], w3, z1); fma2(acc[14], w3, z2); fma2(acc[15], w3, z3);
    }
}

__device__ __forceinline__ void epi2_l0(const ull acc[16], const float* sB2,
                                        __half* outh, int o0, float* sStats) {
#pragma unroll
    for (int r = 0; r < 4; r++) {
        int o = o0 + r;
        float b = sB2[o];
        float2 p0 = upk(acc[r * 4 + 0]), p1 = upk(acc[r * 4 + 1]);
        float2 p2 = upk(acc[r * 4 + 2]), p3 = upk(acc[r * 4 + 3]);
        float f0 = fmaxf(p0.x + b, 0.f), f1 = fmaxf(p0.y + b, 0.f);
        float f2 = fmaxf(p1.x + b, 0.f), f3 = fmaxf(p1.y + b, 0.f);
        float f4 = fmaxf(p2.x + b, 0.f), f5 = fmaxf(p2.y + b, 0.f);
        float f6 = fmaxf(p3.x + b, 0.f), f7 = fmaxf(p3.y + b, 0.f);
        __half2 h0 = __floats2half2_rn(f0, f1);
        __half2 h1 = __floats2half2_rn(f2, f3);
        __half2 h2 = __floats2half2_rn(f4, f5);
        __half2 h3 = __floats2half2_rn(f6, f7);
        uint4 hv;
        hv.x = *(unsigned*)&h0; hv.y = *(unsigned*)&h1;
        hv.z = *(unsigned*)&h2; hv.w = *(unsigned*)&h3;
        *(uint4*)(outh + o * 8) = hv;
        float s = f0 + f1 + f2 + f3 + f4 + f5 + f6 + f7;
        float q = f0*f0 + f1*f1 + f2*f2 + f3*f3 + f4*f4 + f5*f5 + f6*f6 + f7*f7;
        s += __shfl_xor_sync(0xffffffffu, s, 16);
        q += __shfl_xor_sync(0xffffffffu, q, 16);
        if ((threadIdx.x & 16) == 0) {
            atomicAdd(&sStats[o], s);
            atomicAdd(&sStats[64 + o], q);
        }
    }
}

// ---------------- layer 0 (IN_DIM=1) ----------------
__global__ void __launch_bounds__(128) k_layer0(
    const float* __restrict__ x, const float* __restrict__ w10,
    const float* __restrict__ b1, const float* __restrict__ b2) {
    __shared__ float sZ[8 * FEAT];
    __shared__ float sZ0[64];
    __shared__ float sStats[128];
    __shared__ float sB2[64];
    int t = threadIdx.x;
    sStats[t] = 0.f;
    if (t < 64) sB2[t] = b2[t];
    int g = t >> 4, l = t & 15;
    int n = (blockIdx.x << 3) + g;
    if (l < 8) {
        float a = x[n * 8 + l];
        int rs = g_rowptr[n], re = g_rowptr[n + 1];
        for (int e = rs; e < re; e++) a += x[g_srce[e] * 8 + l];
        sZ0[g * 8 + l] = a;
    }
    __syncthreads();
    int o0 = l << 2;
    float zz[8];
#pragma unroll
    for (int m = 0; m < 8; m++) zz[m] = sZ0[g * 8 + m];
#pragma unroll
    for (int r = 0; r < 4; r++) {
        int o = o0 + r;
        float w = w10[o], b = b1[o];
        float4 v0, v1;
        v0.x = fmaxf(w * zz[0] + b, 0.f); v0.y = fmaxf(w * zz[1] + b, 0.f);
        v0.z = fmaxf(w * zz[2] + b, 0.f); v0.w = fmaxf(w * zz[3] + b, 0.f);
        v1.x = fmaxf(w * zz[4] + b, 0.f); v1.y = fmaxf(w * zz[5] + b, 0.f);
        v1.z = fmaxf(w * zz[6] + b, 0.f); v1.w = fmaxf(w * zz[7] + b, 0.f);
        *(float4*)(sZ + (g << 9) + o * 8)     = v0;
        *(float4*)(sZ + (g << 9) + o * 8 + 4) = v1;
    }
    __syncthreads();
    ull acc[16];
    gemm64(sZ + (g << 9), g_Wt2p + o0, acc);
    epi2_l0(acc, sB2, g_hbuf + (size_t)n * FEAT, o0, sStats);
    __syncthreads();
    atomicAdd(&g_stats[t], sStats[t]);
}

// ---------------- gather (layers 1..4): fp16 CSR gather + local BN affine ----
// 64 threads per node; BN affine of previous layer computed per block from g_stats.
__device__ __forceinline__ void acc8(float a[8], uint4 v) {
    float2 p;
    p = __half22float2(*(const __half2*)&v.x); a[0] += p.x; a[1] += p.y;
    p = __half22float2(*(const __half2*)&v.y); a[2] += p.x; a[3] += p.y;
    p = __half22float2(*(const __half2*)&v.z); a[4] += p.x; a[5] += p.y;
    p = __half22float2(*(const __half2*)&v.w); a[6] += p.x; a[7] += p.y;
}

__global__ void __launch_bounds__(256) k_gather(
    int layer, const float* __restrict__ gamma, const float* __restrict__ beta) {
    __shared__ float sSc[64], sSh[64];
    const uint4* __restrict__ in = (const uint4*)g_hbuf;  // 64 uint4 per node row
    int t = threadIdx.x;
    if (t < 64) {   // affine of layer-1 from raw stats (same math as old finalize)
        const float* st = g_stats + (layer - 1) * 128;
        float inv = 1.0f / 160000.0f;
        float mean = st[t] * inv;
        float var = st[64 + t] * inv - mean * mean;
        float sc = gamma[t] * rsqrtf(var + 1e-5f);
        sSc[t] = sc;
        sSh[t] = beta[t] - mean * sc;
    }
    __syncthreads();
    int grp = t >> 6;          // node within block: 0..3
    int l = t & 63;            // channel
    int n = (blockIdx.x << 2) + grp;
    int rs = g_rowptr[n], re = g_rowptr[n + 1];
    float sc = sSc[l], sh = sSh[l];
    float a[8] = {0,0,0,0,0,0,0,0}, b[8] = {0,0,0,0,0,0,0,0};
    acc8(a, in[(size_t)n * 64 + l]);   // self
    int e = rs;
    for (; e + 4 <= re; e += 4) {
        uint4 v0 = in[(size_t)g_srce[e]     * 64 + l];
        uint4 v1 = in[(size_t)g_srce[e + 1] * 64 + l];
        uint4 v2 = in[(size_t)g_srce[e + 2] * 64 + l];
        uint4 v3 = in[(size_t)g_srce[e + 3] * 64 + l];
        acc8(a, v0); acc8(b, v1); acc8(a, v2); acc8(b, v3);
    }
    for (; e < re; e++) acc8(a, in[(size_t)g_srce[e] * 64 + l]);
    float shd = sh * (float)(re - rs + 1);
    float f0 = sc * (a[0] + b[0]) + shd, f1 = sc * (a[1] + b[1]) + shd;
    float f2 = sc * (a[2] + b[2]) + shd, f3 = sc * (a[3] + b[3]) + shd;
    float f4 = sc * (a[4] + b[4]) + shd, f5 = sc * (a[5] + b[5]) + shd;
    float f6 = sc * (a[6] + b[6]) + shd, f7 = sc * (a[7] + b[7]) + shd;
    __half2 h0 = __floats2half2_rn(f0, f1);
    __half2 h1 = __floats2half2_rn(f2, f3);
    __half2 h2 = __floats2half2_rn(f4, f5);
    __half2 h3 = __floats2half2_rn(f6, f7);
    uint4 hv;
    hv.x = *(unsigned*)&h0; hv.y = *(unsigned*)&h1;
    hv.z = *(unsigned*)&h2; hv.w = *(unsigned*)&h3;
    *(uint4*)(g_z16 + (size_t)n * FEAT + (l << 3)) = hv;
}

// ---------------- MLP (layers 1..4): HMMA GEMM pair, padded weight smem ----
// 256 threads = 8 warps, 1 node per warp. Weight rows padded to 144B so the
// 8 ldmatrix row pointers land in distinct bank groups (no crossbar conflicts).
__global__ void __launch_bounds__(256) k_mlp(
    int layer, const float* __restrict__ b1, const float* __restrict__ b2) {
    __shared__ __half sW1[64 * WPAD];   // 9216 B
    __shared__ __half sW2[64 * WPAD];
    __shared__ __half sZ[8 * FEAT];     // 8 node tiles [c64][m8], reused z -> y
    __shared__ float sStats[128];
    __shared__ float sB1[64], sB2[64];
    int t = threadIdx.x;
    int w = t >> 5, lane = t & 31;
    if (t < 128) sStats[t] = 0.f;
    if (t < 64) { sB1[t] = b1[t]; sB2[t] = b2[t]; }
    const uint4* w1src = (const uint4*)(g_W1h + (size_t)(layer - 1) * 4096);
    const uint4* w2src = (const uint4*)(g_W2h + (size_t)layer * 4096);
    const uint4* zsrc  = (const uint4*)(g_z16 + (size_t)(blockIdx.x << 3) * FEAT);
    // stage weights into padded layout: row o at uint4 offset o*9
#pragma unroll
    for (int rep = 0; rep < 2; rep++) {
        int j = t + rep * 256;          // 0..511
        int o = j >> 3, c8 = j & 7;
        ((uint4*)sW1)[o * 9 + c8] = w1src[j];
        ((uint4*)sW2)[o * 9 + c8] = w2src[j];
    }
    ((uint4*)sZ)[t]       = zsrc[t];
    ((uint4*)sZ)[t + 256] = zsrc[t + 256];
    __syncthreads();

    int n = (blockIdx.x << 3) + w;
    uint32_t zbase = smem_u32(sZ + w * FEAT);
    int r = lane >> 2, q = lane & 3;
    int arow = lane & 15, acol = (lane >> 4) << 3;

    // ---- GEMM1 ----
    unsigned bf[4][2];
#pragma unroll
    for (int k = 0; k < 4; k++)
        ldmBt(bf[k], zbase + ((k * 16 + (lane & 15)) * 8) * 2);
    uint32_t w1base = smem_u32(sW1);
    float acc[4][4];
#pragma unroll
    for (int ot = 0; ot < 4; ot++) {
#pragma unroll
        for (int i = 0; i < 4; i++) acc[ot][i] = 0.f;
#pragma unroll
        for (int k = 0; k < 4; k++) {
            unsigned af[4];
            ldmA(af, w1base + (ot * 16 + arow) * (WPAD * 2) + (k * 16 + acol) * 2);
            mma16816(acc[ot], af, bf[k]);
        }
    }
    // epilogue 1: y = relu(acc + b1) -> overwrite own z tile (warp-private)
#pragma unroll
    for (int ot = 0; ot < 4; ot++) {
        int oa = ot * 16 + r, ob = oa + 8;
        float ba = sB1[oa], bb = sB1[ob];
        __half2 ya = __floats2half2_rn(fmaxf(acc[ot][0] + ba, 0.f), fmaxf(acc[ot][1] + ba, 0.f));
        __half2 yb = __floats2half2_rn(fmaxf(acc[ot][2] + bb, 0.f), fmaxf(acc[ot][3] + bb, 0.f));
        *(__half2*)(sZ + w * FEAT + oa * 8 + 2 * q) = ya;
        *(__half2*)(sZ + w * FEAT + ob * 8 + 2 * q) = yb;
    }
    __syncwarp();

    // ---- GEMM2 ----
#pragma unroll
    for (int k = 0; k < 4; k++)
        ldmBt(bf[k], zbase + ((k * 16 + (lane & 15)) * 8) * 2);
    uint32_t w2base = smem_u32(sW2);
#pragma unroll
    for (int ot = 0; ot < 4; ot++) {
#pragma unroll
        for (int i = 0; i < 4; i++) acc[ot][i] = 0.f;
#pragma unroll
        for (int k = 0; k < 4; k++) {
            unsigned af[4];
            ldmA(af, w2base + (ot * 16 + arow) * (WPAD * 2) + (k * 16 + acol) * 2);
            mma16816(acc[ot], af, bf[k]);
        }
    }
    // epilogue 2: h = relu(acc + b2) -> global fp16 + stats
    __half* hrow = g_hbuf + (size_t)n * FEAT;
#pragma unroll
    for (int ot = 0; ot < 4; ot++) {
        int oa = ot * 16 + r, ob = oa + 8;
        float ba = sB2[oa], bb = sB2[ob];
        float f0 = fmaxf(acc[ot][0] + ba, 0.f), f1 = fmaxf(acc[ot][1] + ba, 0.f);
        float f2 = fmaxf(acc[ot][2] + bb, 0.f), f3 = fmaxf(acc[ot][3] + bb, 0.f);
        *(__half2*)(hrow + oa * 8 + 2 * q) = __floats2half2_rn(f0, f1);
        *(__half2*)(hrow + ob * 8 + 2 * q) = __floats2half2_rn(f2, f3);
        float sa = f0 + f1, qa = f0 * f0 + f1 * f1;
        float sb = f2 + f3, qb = f2 * f2 + f3 * f3;
        sa += __shfl_xor_sync(0xffffffffu, sa, 1); sa += __shfl_xor_sync(0xffffffffu, sa, 2);
        qa += __shfl_xor_sync(0xffffffffu, qa, 1); qa += __shfl_xor_sync(0xffffffffu, qa, 2);
        sb += __shfl_xor_sync(0xffffffffu, sb, 1); sb += __shfl_xor_sync(0xffffffffu, sb, 2);
        qb += __shfl_xor_sync(0xffffffffu, qb, 1); qb += __shfl_xor_sync(0xffffffffu, qb, 2);
        if (q == 0) {
            atomicAdd(&sStats[oa], sa);
            atomicAdd(&sStats[64 + oa], qa);
            atomicAdd(&sStats[ob], sb);
            atomicAdd(&sStats[64 + ob], qb);
        }
    }
    __syncthreads();
    if (t < 128) atomicAdd(&g_stats[layer * 128 + t], sStats[t]);
}

// ---------------- pooling + head ----------------
__global__ void k_pool() {   // reads raw layer-4 fp16 output in g_hbuf
    int t = threadIdx.x;     // 256 threads; 2 consecutive elements each
    float a0 = 0.f, a1 = 0.f;
    for (int n = blockIdx.x; n < N_NODES; n += gridDim.x) {
        __half2 v = *(const __half2*)(g_hbuf + (size_t)n * FEAT + t * 2);
        float2 p = __half22float2(v);
        a0 += p.x; a1 += p.y;
    }
    atomicAdd(&g_pool[t * 2], a0);
    atomicAdd(&g_pool[t * 2 + 1], a1);
}

__global__ void k_final(const float* __restrict__ gamma, const float* __restrict__ beta,
                        const float* __restrict__ wout, const float* __restrict__ bout,
                        float* __restrict__ o) {
    __shared__ float sSc[64], sSh[64];
    int t = threadIdx.x;   // 64 threads
    {   // layer-4 BN affine from raw stats
        const float* st = g_stats + 4 * 128;
        float inv = 1.0f / 160000.0f;
        float mean = st[t] * inv;
        float var = st[64 + t] * inv - mean * mean;
        float sc = gamma[t] * rsqrtf(var + 1e-5f);
        sSc[t] = sc;
        sSh[t] = beta[t] - mean * sc;
    }
    __syncthreads();
    if (t < 8) {
        float acc = bout[0];
        for (int c = 0; c < 64; c++)
            acc += wout[c] * (sSc[c] * g_pool[c * 8 + t] * (1.0f / N_NODES) + sSh[c]);
        o[t] = 1.0f / (1.0f + expf(-acc));
    }
}

// ---------------- launch ----------------
extern "C" void kernel_launch(void* const* d_in, const int* in_sizes, int n_in,
                              void* d_out, int out_size) {
    const float* x     = (const float*)d_in[0];
    const void*  ei    = d_in[1];
    // d_in[2] = batch (unused, all zeros)
    const float* w10   = (const float*)d_in[3];
    const float* w1    = (const float*)d_in[4];
    const float* b1    = (const float*)d_in[5];
    const float* w2    = (const float*)d_in[6];
    const float* b2    = (const float*)d_in[7];
    const float* gamma = (const float*)d_in[8];
    const float* beta  = (const float*)d_in[9];
    const float* wout  = (const float*)d_in[10];
    const float* bout  = (const float*)d_in[11];
    float* out = (float*)d_out;

    k_init<<<(N_NODES + 255) / 256, 256>>>(ei);
    k_prep<<<(9 * 4096 + 255) / 256, 256>>>(w1, w2);
    k_hist<<<(N_EDGES + 255) / 256, 256>>>(ei);
    k_scan<<<1, 1024>>>();
    k_fill<<<(N_EDGES + 255) / 256, 256>>>(ei);

    k_layer0<<<N_NODES / 8, 128>>>(x, w10, b1, b2);
    for (int i = 1; i <= 4; i++) {
        k_gather<<<N_NODES / 4, 256>>>(i, gamma + (i - 1) * 64, beta + (i - 1) * 64);
        k_mlp<<<N_NODES / 8, 256>>>(i, b1 + i * 64, b2 + i * 64);
    }
    k_pool<<<256, 256>>>();
    k_final<<<1, 64>>>(gamma + 4 * 64, beta + 4 * 64, wout, bout, out);
}

// round 13
// speedup vs baseline: 1.9870x; 1.0370x over previous
#include <cuda_runtime.h>
#include <cuda_fp16.h>
#include <cstdint>

// GIN: 5 layers, N=20000 nodes, E=320000 edges, HIDDEN=64, M=8.
//  - CSR build per launch (vectorized histogram + shfl scan + vectorized fill).
//  - h/z fp16, L2-resident. k_gather: fp16 CSR gather + local BN-affine -> z.
//  - k_mlp: HMMA GEMM pair, weight smem rows padded to 144B (conflict-free
//    ldmatrix). Layer-4 epilogue also accumulates the global mean-pool.
//  - k_final folds layer-4 BN into the head.

#define N_NODES 20000
#define N_EDGES 320000
#define HID 64
#define MDIM 8
#define FEAT (HID*MDIM)   // 512 elements per node
#define WPAD 72           // padded halves per weight row (144B, 9 uint4)

typedef unsigned long long ull;

// ---------------- device scratch ----------------
__device__ __half g_hbuf[N_NODES * FEAT];   // h fp16 (gather + pool source)
__device__ __half g_z16[N_NODES * FEAT];    // z fp16 scratch
__device__ int    g_rowptr[N_NODES + 1];
__device__ int    g_count[N_NODES];
__device__ int    g_fill[N_NODES];
__device__ int    g_srce[N_EDGES];
__device__ float  g_stats[5 * 128];         // per layer: sum[64], sumsq[64]
__device__ ull    g_Wt2p[4096];             // W2 layer 0 (FFMA2 path), [c][o] pairs
__device__ __half g_W1h[4 * 4096];          // W1 layers 1..4, [o][c] fp16
__device__ __half g_W2h[5 * 4096];          // W2 layers 0..4, [o][c] fp16
__device__ float  g_pool[FEAT];
__device__ int    g_is64;

// ---------------- helpers ----------------
__device__ __forceinline__ ull pk2(float a, float b) {
    ull r; asm("mov.b64 %0, {%1, %2};" : "=l"(r) : "f"(a), "f"(b)); return r;
}
__device__ __forceinline__ float2 upk(ull v) {
    float2 r; asm("mov.b64 {%0, %1}, %2;" : "=f"(r.x), "=f"(r.y) : "l"(v)); return r;
}
__device__ __forceinline__ void fma2(ull& a, ull b, ull c) {
    asm("fma.rn.f32x2 %0, %1, %2, %0;" : "+l"(a) : "l"(b), "l"(c));
}
__device__ __forceinline__ uint32_t smem_u32(const void* p) {
    return (uint32_t)__cvta_generic_to_shared(p);
}
__device__ __forceinline__ void ldmA(unsigned a[4], uint32_t addr) {
    asm volatile("ldmatrix.sync.aligned.m8n8.x4.shared.b16 {%0,%1,%2,%3}, [%4];"
        : "=r"(a[0]), "=r"(a[1]), "=r"(a[2]), "=r"(a[3]) : "r"(addr));
}
__device__ __forceinline__ void ldmBt(unsigned b[2], uint32_t addr) {
    asm volatile("ldmatrix.sync.aligned.m8n8.x2.trans.shared.b16 {%0,%1}, [%2];"
        : "=r"(b[0]), "=r"(b[1]) : "r"(addr));
}
__device__ __forceinline__ void mma16816(float d[4], const unsigned a[4], const unsigned b[2]) {
    asm volatile("mma.sync.aligned.m16n8k16.row.col.f32.f16.f16.f32 "
        "{%0,%1,%2,%3}, {%4,%5,%6,%7}, {%8,%9}, {%0,%1,%2,%3};"
        : "+f"(d[0]), "+f"(d[1]), "+f"(d[2]), "+f"(d[3])
        : "r"(a[0]), "r"(a[1]), "r"(a[2]), "r"(a[3]), "r"(b[0]), "r"(b[1]));
}

// ---------------- setup kernels ----------------
__global__ void k_init(const void* ei) {
    __shared__ int s_ok;
    if (threadIdx.x == 0) s_ok = 1;
    __syncthreads();
    int i = blockIdx.x * blockDim.x + threadIdx.x;
    if (i < N_NODES) { g_count[i] = 0; g_fill[i] = 0; }
    if (i < 5 * 128) g_stats[i] = 0.f;
    if (i < FEAT)    g_pool[i] = 0.f;
    if (blockIdx.x == 0 && threadIdx.x < 64) {
        if (((const ull*)ei)[threadIdx.x] >= (ull)N_NODES) atomicExch(&s_ok, 0);
    }
    __syncthreads();
    if (blockIdx.x == 0 && threadIdx.x == 0) g_is64 = s_ok;
}

// histogram: 4 edges per thread, vectorized loads
__global__ void k_hist(const void* ei) {
    int i = blockIdx.x * blockDim.x + threadIdx.x;
    if (i * 4 >= N_EDGES) return;
    int d0, d1, d2, d3;
    if (g_is64) {
        const longlong2* pd = (const longlong2*)((const long long*)ei + N_EDGES);
        longlong2 a = pd[i * 2], b = pd[i * 2 + 1];
        d0 = (int)a.x; d1 = (int)a.y; d2 = (int)b.x; d3 = (int)b.y;
    } else {
        int4 a = ((const int4*)((const int*)ei + N_EDGES))[i];
        d0 = a.x; d1 = a.y; d2 = a.z; d3 = a.w;
    }
    atomicAdd(&g_count[d0], 1);
    atomicAdd(&g_count[d1], 1);
    atomicAdd(&g_count[d2], 1);
    atomicAdd(&g_count[d3], 1);
}

// shfl-based single-block scan: 2 barriers instead of 20
__global__ void k_scan() {   // 1024 threads
    __shared__ int warpsum[32];
    const int CH = 20;
    int t = threadIdx.x;
    int lane = t & 31, wid = t >> 5;
    int base = t * CH;
    int raw[CH];
    if (base + CH <= N_NODES) {
#pragma unroll
        for (int v4 = 0; v4 < 5; v4++) {
            int4 v = *(const int4*)(g_count + base + v4 * 4);
            raw[v4 * 4 + 0] = v.x; raw[v4 * 4 + 1] = v.y;
            raw[v4 * 4 + 2] = v.z; raw[v4 * 4 + 3] = v.w;
        }
    } else {
#pragma unroll
        for (int j = 0; j < CH; j++)
            raw[j] = (base + j < N_NODES) ? g_count[base + j] : 0;
    }
    int vals[CH];
    int local = 0;
#pragma unroll
    for (int j = 0; j < CH; j++) { vals[j] = local; local += raw[j]; }
    // warp inclusive scan of per-thread totals
    int inc = local;
#pragma unroll
    for (int off = 1; off < 32; off <<= 1) {
        int v = __shfl_up_sync(0xffffffffu, inc, off);
        if (lane >= off) inc += v;
    }
    if (lane == 31) warpsum[wid] = inc;
    __syncthreads();
    if (wid == 0) {
        int v = warpsum[lane];
        int inc2 = v;
#pragma unroll
        for (int off = 1; off < 32; off <<= 1) {
            int u = __shfl_up_sync(0xffffffffu, inc2, off);
            if (lane >= off) inc2 += u;
        }
        warpsum[lane] = inc2 - v;   // exclusive warp offsets
    }
    __syncthreads();
    int toff = warpsum[wid] + inc - local;   // exclusive prefix for this thread
#pragma unroll
    for (int j = 0; j < CH; j++) {
        int i = base + j;
        if (i < N_NODES) g_rowptr[i] = toff + vals[j];
    }
    if (t == 1023) g_rowptr[N_NODES] = toff + local;
}

// fill: 4 edges per thread, vectorized loads
__global__ void k_fill(const void* ei) {
    int i = blockIdx.x * blockDim.x + threadIdx.x;
    if (i * 4 >= N_EDGES) return;
    int s0, s1, s2, s3, d0, d1, d2, d3;
    if (g_is64) {
        const longlong2* ps = (const longlong2*)ei;
        const longlong2* pd = (const longlong2*)((const long long*)ei + N_EDGES);
        longlong2 a = ps[i * 2], b = ps[i * 2 + 1];
        longlong2 c = pd[i * 2], d = pd[i * 2 + 1];
        s0 = (int)a.x; s1 = (int)a.y; s2 = (int)b.x; s3 = (int)b.y;
        d0 = (int)c.x; d1 = (int)c.y; d2 = (int)d.x; d3 = (int)d.y;
    } else {
        int4 a = ((const int4*)ei)[i];
        int4 c = ((const int4*)((const int*)ei + N_EDGES))[i];
        s0 = a.x; s1 = a.y; s2 = a.z; s3 = a.w;
        d0 = c.x; d1 = c.y; d2 = c.z; d3 = c.w;
    }
    g_srce[g_rowptr[d0] + atomicAdd(&g_fill[d0], 1)] = s0;
    g_srce[g_rowptr[d1] + atomicAdd(&g_fill[d1], 1)] = s1;
    g_srce[g_rowptr[d2] + atomicAdd(&g_fill[d2], 1)] = s2;
    g_srce[g_rowptr[d3] + atomicAdd(&g_fill[d3], 1)] = s3;
}

// weight prep: fp16 copies of W1 (1..4) / W2 (0..4) [o][c]; fp32 pairs for layer0 W2.
__global__ void k_prep(const float* __restrict__ w1, const float* __restrict__ w2) {
    int idx = blockIdx.x * blockDim.x + threadIdx.x;
    if (idx < 4 * 4096) {
        g_W1h[idx] = __float2half(w1[idx]);
    } else if (idx < 9 * 4096) {
        int j = idx - 4 * 4096;
        float v = w2[j];
        g_W2h[j] = __float2half(v);
        if (j < 4096) {
            int o = j >> 6, c = j & 63;
            g_Wt2p[(c << 6) + o] = pk2(v, v);
        }
    }
}

// ---------------- layer0 FFMA2 GEMM core (once per launch) ----------------
__device__ __forceinline__ void gemm64(const float* sIn, const ull* __restrict__ Wp,
                                       ull acc[16]) {
#pragma unroll
    for (int i = 0; i < 16; i++) acc[i] = 0ULL;
#pragma unroll 8
    for (int c = 0; c < 64; c++) {
        ulonglong2 wa = *(const ulonglong2*)(Wp + (c << 6));
        ulonglong2 wb = *(const ulonglong2*)(Wp + (c << 6) + 2);
        ulonglong2 za = *(const ulonglong2*)(sIn + (c << 3));
        ulonglong2 zb = *(const ulonglong2*)(sIn + (c << 3) + 4);
        ull w0 = wa.x, w1 = wa.y, w2 = wb.x, w3 = wb.y;
        ull z0 = za.x, z1 = za.y, z2 = zb.x, z3 = zb.y;
        fma2(acc[0],  w0, z0); fma2(acc[1],  w0, z1); fma2(acc[2],  w0, z2); fma2(acc[3],  w0, z3);
        fma2(acc[4],  w1, z0); fma2(acc[5],  w1, z1); fma2(acc[6],  w1, z2); fma2(acc[7],  w1, z3);
        fma2(acc[8],  w2, z0); fma2(acc[9],  w2, z1); fma2(acc[10], w2, z2); fma2(acc[11], w2, z3);
        fma2(acc[12], w3, z0); fma2(acc[13], w3, z1); fma2(acc[14], w3, z2); fma2(acc[15], w3, z3);
    }
}

__device__ __forceinline__ void epi2_l0(const ull acc[16], const float* sB2,
                                        __half* outh, int o0, float* sStats) {
#pragma unroll
    for (int r = 0; r < 4; r++) {
        int o = o0 + r;
        float b = sB2[o];
        float2 p0 = upk(acc[r * 4 + 0]), p1 = upk(acc[r * 4 + 1]);
        float2 p2 = upk(acc[r * 4 + 2]), p3 = upk(acc[r * 4 + 3]);
        float f0 = fmaxf(p0.x + b, 0.f), f1 = fmaxf(p0.y + b, 0.f);
        float f2 = fmaxf(p1.x + b, 0.f), f3 = fmaxf(p1.y + b, 0.f);
        float f4 = fmaxf(p2.x + b, 0.f), f5 = fmaxf(p2.y + b, 0.f);
        float f6 = fmaxf(p3.x + b, 0.f), f7 = fmaxf(p3.y + b, 0.f);
        __half2 h0 = __floats2half2_rn(f0, f1);
        __half2 h1 = __floats2half2_rn(f2, f3);
        __half2 h2 = __floats2half2_rn(f4, f5);
        __half2 h3 = __floats2half2_rn(f6, f7);
        uint4 hv;
        hv.x = *(unsigned*)&h0; hv.y = *(unsigned*)&h1;
        hv.z = *(unsigned*)&h2; hv.w = *(unsigned*)&h3;
        *(uint4*)(outh + o * 8) = hv;
        float s = f0 + f1 + f2 + f3 + f4 + f5 + f6 + f7;
        float q = f0*f0 + f1*f1 + f2*f2 + f3*f3 + f4*f4 + f5*f5 + f6*f6 + f7*f7;
        s += __shfl_xor_sync(0xffffffffu, s, 16);
        q += __shfl_xor_sync(0xffffffffu, q, 16);
        if ((threadIdx.x & 16) == 0) {
            atomicAdd(&sStats[o], s);
            atomicAdd(&sStats[64 + o], q);
        }
    }
}

// ---------------- layer 0 (IN_DIM=1) ----------------
__global__ void __launch_bounds__(128) k_layer0(
    const float* __restrict__ x, const float* __restrict__ w10,
    const float* __restrict__ b1, const float* __restrict__ b2) {
    __shared__ float sZ[8 * FEAT];
    __shared__ float sZ0[64];
    __shared__ float sStats[128];
    __shared__ float sB2[64];
    int t = threadIdx.x;
    sStats[t] = 0.f;
    if (t < 64) sB2[t] = b2[t];
    int g = t >> 4, l = t & 15;
    int n = (blockIdx.x << 3) + g;
    if (l < 8) {
        float a = x[n * 8 + l];
        int rs = g_rowptr[n], re = g_rowptr[n + 1];
        for (int e = rs; e < re; e++) a += x[g_srce[e] * 8 + l];
        sZ0[g * 8 + l] = a;
    }
    __syncthreads();
    int o0 = l << 2;
    float zz[8];
#pragma unroll
    for (int m = 0; m < 8; m++) zz[m] = sZ0[g * 8 + m];
#pragma unroll
    for (int r = 0; r < 4; r++) {
        int o = o0 + r;
        float w = w10[o], b = b1[o];
        float4 v0, v1;
        v0.x = fmaxf(w * zz[0] + b, 0.f); v0.y = fmaxf(w * zz[1] + b, 0.f);
        v0.z = fmaxf(w * zz[2] + b, 0.f); v0.w = fmaxf(w * zz[3] + b, 0.f);
        v1.x = fmaxf(w * zz[4] + b, 0.f); v1.y = fmaxf(w * zz[5] + b, 0.f);
        v1.z = fmaxf(w * zz[6] + b, 0.f); v1.w = fmaxf(w * zz[7] + b, 0.f);
        *(float4*)(sZ + (g << 9) + o * 8)     = v0;
        *(float4*)(sZ + (g << 9) + o * 8 + 4) = v1;
    }
    __syncthreads();
    ull acc[16];
    gemm64(sZ + (g << 9), g_Wt2p + o0, acc);
    epi2_l0(acc, sB2, g_hbuf + (size_t)n * FEAT, o0, sStats);
    __syncthreads();
    atomicAdd(&g_stats[t], sStats[t]);
}

// ---------------- gather (layers 1..4): fp16 CSR gather + local BN affine ----
__device__ __forceinline__ void acc8(float a[8], uint4 v) {
    float2 p;
    p = __half22float2(*(const __half2*)&v.x); a[0] += p.x; a[1] += p.y;
    p = __half22float2(*(const __half2*)&v.y); a[2] += p.x; a[3] += p.y;
    p = __half22float2(*(const __half2*)&v.z); a[4] += p.x; a[5] += p.y;
    p = __half22float2(*(const __half2*)&v.w); a[6] += p.x; a[7] += p.y;
}

__global__ void __launch_bounds__(256) k_gather(
    int layer, const float* __restrict__ gamma, const float* __restrict__ beta) {
    __shared__ float sSc[64], sSh[64];
    const uint4* __restrict__ in = (const uint4*)g_hbuf;
    int t = threadIdx.x;
    if (t < 64) {
        const float* st = g_stats + (layer - 1) * 128;
        float inv = 1.0f / 160000.0f;
        float mean = st[t] * inv;
        float var = st[64 + t] * inv - mean * mean;
        float sc = gamma[t] * rsqrtf(var + 1e-5f);
        sSc[t] = sc;
        sSh[t] = beta[t] - mean * sc;
    }
    __syncthreads();
    int grp = t >> 6;
    int l = t & 63;
    int n = (blockIdx.x << 2) + grp;
    int rs = g_rowptr[n], re = g_rowptr[n + 1];
    float sc = sSc[l], sh = sSh[l];
    float a[8] = {0,0,0,0,0,0,0,0}, b[8] = {0,0,0,0,0,0,0,0};
    acc8(a, in[(size_t)n * 64 + l]);   // self
    int e = rs;
    for (; e + 4 <= re; e += 4) {
        uint4 v0 = in[(size_t)g_srce[e]     * 64 + l];
        uint4 v1 = in[(size_t)g_srce[e + 1] * 64 + l];
        uint4 v2 = in[(size_t)g_srce[e + 2] * 64 + l];
        uint4 v3 = in[(size_t)g_srce[e + 3] * 64 + l];
        acc8(a, v0); acc8(b, v1); acc8(a, v2); acc8(b, v3);
    }
    for (; e < re; e++) acc8(a, in[(size_t)g_srce[e] * 64 + l]);
    float shd = sh * (float)(re - rs + 1);
    float f0 = sc * (a[0] + b[0]) + shd, f1 = sc * (a[1] + b[1]) + shd;
    float f2 = sc * (a[2] + b[2]) + shd, f3 = sc * (a[3] + b[3]) + shd;
    float f4 = sc * (a[4] + b[4]) + shd, f5 = sc * (a[5] + b[5]) + shd;
    float f6 = sc * (a[6] + b[6]) + shd, f7 = sc * (a[7] + b[7]) + shd;
    __half2 h0 = __floats2half2_rn(f0, f1);
    __half2 h1 = __floats2half2_rn(f2, f3);
    __half2 h2 = __floats2half2_rn(f4, f5);
    __half2 h3 = __floats2half2_rn(f6, f7);
    uint4 hv;
    hv.x = *(unsigned*)&h0; hv.y = *(unsigned*)&h1;
    hv.z = *(unsigned*)&h2; hv.w = *(unsigned*)&h3;
    *(uint4*)(g_z16 + (size_t)n * FEAT + (l << 3)) = hv;
}

// ---------------- MLP (layers 1..4): HMMA GEMM pair, padded weight smem ----
// Layer 4 also accumulates the global mean-pool in its epilogue.
__global__ void __launch_bounds__(256) k_mlp(
    int layer, const float* __restrict__ b1, const float* __restrict__ b2) {
    __shared__ __half sW1[64 * WPAD];
    __shared__ __half sW2[64 * WPAD];
    __shared__ __half sZ[8 * FEAT];
    __shared__ float sStats[128];
    __shared__ float sPool[FEAT];
    __shared__ float sB1[64], sB2[64];
    int t = threadIdx.x;
    int w = t >> 5, lane = t & 31;
    if (t < 128) sStats[t] = 0.f;
    if (t < 64) { sB1[t] = b1[t]; sB2[t] = b2[t]; }
    if (layer == 4) { sPool[t] = 0.f; sPool[t + 256] = 0.f; }
    const uint4* w1src = (const uint4*)(g_W1h + (size_t)(layer - 1) * 4096);
    const uint4* w2src = (const uint4*)(g_W2h + (size_t)layer * 4096);
    const uint4* zsrc  = (const uint4*)(g_z16 + (size_t)(blockIdx.x << 3) * FEAT);
#pragma unroll
    for (int rep = 0; rep < 2; rep++) {
        int j = t + rep * 256;
        int o = j >> 3, c8 = j & 7;
        ((uint4*)sW1)[o * 9 + c8] = w1src[j];
        ((uint4*)sW2)[o * 9 + c8] = w2src[j];
    }
    ((uint4*)sZ)[t]       = zsrc[t];
    ((uint4*)sZ)[t + 256] = zsrc[t + 256];
    __syncthreads();

    int n = (blockIdx.x << 3) + w;
    uint32_t zbase = smem_u32(sZ + w * FEAT);
    int r = lane >> 2, q = lane & 3;
    int arow = lane & 15, acol = (lane >> 4) << 3;

    // ---- GEMM1 ----
    unsigned bf[4][2];
#pragma unroll
    for (int k = 0; k < 4; k++)
        ldmBt(bf[k], zbase + ((k * 16 + (lane & 15)) * 8) * 2);
    uint32_t w1base = smem_u32(sW1);
    float acc[4][4];
#pragma unroll
    for (int ot = 0; ot < 4; ot++) {
#pragma unroll
        for (int i = 0; i < 4; i++) acc[ot][i] = 0.f;
#pragma unroll
        for (int k = 0; k < 4; k++) {
            unsigned af[4];
            ldmA(af, w1base + (ot * 16 + arow) * (WPAD * 2) + (k * 16 + acol) * 2);
            mma16816(acc[ot], af, bf[k]);
        }
    }
#pragma unroll
    for (int ot = 0; ot < 4; ot++) {
        int oa = ot * 16 + r, ob = oa + 8;
        float ba = sB1[oa], bb = sB1[ob];
        __half2 ya = __floats2half2_rn(fmaxf(acc[ot][0] + ba, 0.f), fmaxf(acc[ot][1] + ba, 0.f));
        __half2 yb = __floats2half2_rn(fmaxf(acc[ot][2] + bb, 0.f), fmaxf(acc[ot][3] + bb, 0.f));
        *(__half2*)(sZ + w * FEAT + oa * 8 + 2 * q) = ya;
        *(__half2*)(sZ + w * FEAT + ob * 8 + 2 * q) = yb;
    }
    __syncwarp();

    // ---- GEMM2 ----
#pragma unroll
    for (int k = 0; k < 4; k++)
        ldmBt(bf[k], zbase + ((k * 16 + (lane & 15)) * 8) * 2);
    uint32_t w2base = smem_u32(sW2);
#pragma unroll
    for (int ot = 0; ot < 4; ot++) {
#pragma unroll
        for (int i = 0; i < 4; i++) acc[ot][i] = 0.f;
#pragma unroll
        for (int k = 0; k < 4; k++) {
            unsigned af[4];
            ldmA(af, w2base + (ot * 16 + arow) * (WPAD * 2) + (k * 16 + acol) * 2);
            mma16816(acc[ot], af, bf[k]);
        }
    }
    // epilogue 2: h = relu(acc + b2) -> global fp16 + stats (+ pool on layer 4)
    __half* hrow = g_hbuf + (size_t)n * FEAT;
#pragma unroll
    for (int ot = 0; ot < 4; ot++) {
        int oa = ot * 16 + r, ob = oa + 8;
        float ba = sB2[oa], bb = sB2[ob];
        float f0 = fmaxf(acc[ot][0] + ba, 0.f), f1 = fmaxf(acc[ot][1] + ba, 0.f);
        float f2 = fmaxf(acc[ot][2] + bb, 0.f), f3 = fmaxf(acc[ot][3] + bb, 0.f);
        *(__half2*)(hrow + oa * 8 + 2 * q) = __floats2half2_rn(f0, f1);
        *(__half2*)(hrow + ob * 8 + 2 * q) = __floats2half2_rn(f2, f3);
        if (layer == 4) {
            atomicAdd(&sPool[oa * 8 + 2 * q],     f0);
            atomicAdd(&sPool[oa * 8 + 2 * q + 1], f1);
            atomicAdd(&sPool[ob * 8 + 2 * q],     f2);
            atomicAdd(&sPool[ob * 8 + 2 * q + 1], f3);
        }
        float sa = f0 + f1, qa = f0 * f0 + f1 * f1;
        float sb = f2 + f3, qb = f2 * f2 + f3 * f3;
        sa += __shfl_xor_sync(0xffffffffu, sa, 1); sa += __shfl_xor_sync(0xffffffffu, sa, 2);
        qa += __shfl_xor_sync(0xffffffffu, qa, 1); qa += __shfl_xor_sync(0xffffffffu, qa, 2);
        sb += __shfl_xor_sync(0xffffffffu, sb, 1); sb += __shfl_xor_sync(0xffffffffu, sb, 2);
        qb += __shfl_xor_sync(0xffffffffu, qb, 1); qb += __shfl_xor_sync(0xffffffffu, qb, 2);
        if (q == 0) {
            atomicAdd(&sStats[oa], sa);
            atomicAdd(&sStats[64 + oa], qa);
            atomicAdd(&sStats[ob], sb);
            atomicAdd(&sStats[64 + ob], qb);
        }
    }
    __syncthreads();
    if (t < 128) atomicAdd(&g_stats[layer * 128 + t], sStats[t]);
    if (layer == 4) {
        atomicAdd(&g_pool[t], sPool[t]);
        atomicAdd(&g_pool[t + 256], sPool[t + 256]);
    }
}

// ---------------- head ----------------
__global__ void k_final(const float* __restrict__ gamma, const float* __restrict__ beta,
                        const float* __restrict__ wout, const float* __restrict__ bout,
                        float* __restrict__ o) {
    __shared__ float sSc[64], sSh[64];
    int t = threadIdx.x;   // 64 threads
    {
        const float* st = g_stats + 4 * 128;
        float inv = 1.0f / 160000.0f;
        float mean = st[t] * inv;
        float var = st[64 + t] * inv - mean * mean;
        float sc = gamma[t] * rsqrtf(var + 1e-5f);
        sSc[t] = sc;
        sSh[t] = beta[t] - mean * sc;
    }
    __syncthreads();
    if (t < 8) {
        float acc = bout[0];
        for (int c = 0; c < 64; c++)
            acc += wout[c] * (sSc[c] * g_pool[c * 8 + t] * (1.0f / N_NODES) + sSh[c]);
        o[t] = 1.0f / (1.0f + expf(-acc));
    }
}

// ---------------- launch ----------------
extern "C" void kernel_launch(void* const* d_in, const int* in_sizes, int n_in,
                              void* d_out, int out_size) {
    const float* x     = (const float*)d_in[0];
    const void*  ei    = d_in[1];
    // d_in[2] = batch (unused, all zeros)
    const float* w10   = (const float*)d_in[3];
    const float* w1    = (const float*)d_in[4];
    const float* b1    = (const float*)d_in[5];
    const float* w2    = (const float*)d_in[6];
    const float* b2    = (const float*)d_in[7];
    const float* gamma = (const float*)d_in[8];
    const float* beta  = (const float*)d_in[9];
    const float* wout  = (const float*)d_in[10];
    const float* bout  = (const float*)d_in[11];
    float* out = (float*)d_out;

    k_init<<<(N_NODES + 255) / 256, 256>>>(ei);
    k_prep<<<(9 * 4096 + 255) / 256, 256>>>(w1, w2);
    k_hist<<<(N_EDGES / 4 + 255) / 256, 256>>>(ei);
    k_scan<<<1, 1024>>>();
    k_fill<<<(N_EDGES / 4 + 255) / 256, 256>>>(ei);

    k_layer0<<<N_NODES / 8, 128>>>(x, w10, b1, b2);
    for (int i = 1; i <= 4; i++) {
        k_gather<<<N_NODES / 4, 256>>>(i, gamma + (i - 1) * 64, beta + (i - 1) * 64);
        k_mlp<<<N_NODES / 8, 256>>>(i, b1 + i * 64, b2 + i * 64);
    }
    k_final<<<1, 64>>>(gamma + 4 * 64, beta + 4 * 64, wout, bout, out);
}

// round 15
// speedup vs baseline: 2.4034x; 1.2096x over previous
#include <cuda_runtime.h>
#include <cuda_fp16.h>
#include <cstdint>

// GIN: 5 layers, N=20000 nodes, E=320000 edges, HIDDEN=64, M=8.
//  - CSR build per launch (vectorized histogram + shfl scan + vectorized fill).
//  - h/z fp16, L2-resident. k_gather: fp16 CSR gather + local BN-affine -> z.
//  - k_layer0 + k_mlp: HMMA GEMM(s), weight smem rows padded to 144B
//    (conflict-free ldmatrix). Layer-4 epilogue accumulates the mean-pool.
//  - k_final folds layer-4 BN into the head.

#define N_NODES 20000
#define N_EDGES 320000
#define HID 64
#define MDIM 8
#define FEAT (HID*MDIM)   // 512 elements per node
#define WPAD 72           // padded halves per weight row (144B, 9 uint4)

typedef unsigned long long ull;

// ---------------- device scratch ----------------
__device__ __half g_hbuf[N_NODES * FEAT];   // h fp16 (gather + pool source)
__device__ __half g_z16[N_NODES * FEAT];    // z fp16 scratch
__device__ int    g_rowptr[N_NODES + 1];
__device__ int    g_count[N_NODES];
__device__ int    g_fill[N_NODES];
__device__ int    g_srce[N_EDGES];
__device__ float  g_stats[5 * 128];         // per layer: sum[64], sumsq[64]
__device__ __half g_W1h[4 * 4096];          // W1 layers 1..4, [o][c] fp16
__device__ __half g_W2h[5 * 4096];          // W2 layers 0..4, [o][c] fp16
__device__ float  g_pool[FEAT];
__device__ int    g_is64;

// ---------------- helpers ----------------
__device__ __forceinline__ uint32_t smem_u32(const void* p) {
    return (uint32_t)__cvta_generic_to_shared(p);
}
__device__ __forceinline__ void ldmA(unsigned a[4], uint32_t addr) {
    asm volatile("ldmatrix.sync.aligned.m8n8.x4.shared.b16 {%0,%1,%2,%3}, [%4];"
        : "=r"(a[0]), "=r"(a[1]), "=r"(a[2]), "=r"(a[3]) : "r"(addr));
}
__device__ __forceinline__ void ldmBt(unsigned b[2], uint32_t addr) {
    asm volatile("ldmatrix.sync.aligned.m8n8.x2.trans.shared.b16 {%0,%1}, [%2];"
        : "=r"(b[0]), "=r"(b[1]) : "r"(addr));
}
__device__ __forceinline__ void mma16816(float d[4], const unsigned a[4], const unsigned b[2]) {
    asm volatile("mma.sync.aligned.m16n8k16.row.col.f32.f16.f16.f32 "
        "{%0,%1,%2,%3}, {%4,%5,%6,%7}, {%8,%9}, {%0,%1,%2,%3};"
        : "+f"(d[0]), "+f"(d[1]), "+f"(d[2]), "+f"(d[3])
        : "r"(a[0]), "r"(a[1]), "r"(a[2]), "r"(a[3]), "r"(b[0]), "r"(b[1]));
}

// ---------------- setup: init + dtype detect + weight fp16 prep ----------------
__global__ void k_init(const void* ei, const float* __restrict__ w1,
                       const float* __restrict__ w2) {
    __shared__ int s_ok;
    if (threadIdx.x == 0) s_ok = 1;
    __syncthreads();
    int i = blockIdx.x * blockDim.x + threadIdx.x;
    if (i < N_NODES) { g_count[i] = 0; g_fill[i] = 0; }
    if (i < 5 * 128) g_stats[i] = 0.f;
    if (i < FEAT)    g_pool[i] = 0.f;
    if (i < 4 * 4096) g_W1h[i] = __float2half(w1[i]);
    if (i < 5 * 4096) g_W2h[i] = __float2half(w2[i]);
    if (blockIdx.x == 0 && threadIdx.x < 64) {
        if (((const ull*)ei)[threadIdx.x] >= (ull)N_NODES) atomicExch(&s_ok, 0);
    }
    __syncthreads();
    if (blockIdx.x == 0 && threadIdx.x == 0) g_is64 = s_ok;
}

// histogram: 4 edges per thread, vectorized loads
__global__ void k_hist(const void* ei) {
    int i = blockIdx.x * blockDim.x + threadIdx.x;
    if (i * 4 >= N_EDGES) return;
    int d0, d1, d2, d3;
    if (g_is64) {
        const longlong2* pd = (const longlong2*)((const long long*)ei + N_EDGES);
        longlong2 a = pd[i * 2], b = pd[i * 2 + 1];
        d0 = (int)a.x; d1 = (int)a.y; d2 = (int)b.x; d3 = (int)b.y;
    } else {
        int4 a = ((const int4*)((const int*)ei + N_EDGES))[i];
        d0 = a.x; d1 = a.y; d2 = a.z; d3 = a.w;
    }
    atomicAdd(&g_count[d0], 1);
    atomicAdd(&g_count[d1], 1);
    atomicAdd(&g_count[d2], 1);
    atomicAdd(&g_count[d3], 1);
}

// shfl scan; int4 loads AND int4 stores (STG.128 issue cost, not 20x STG.32)
__global__ void k_scan() {   // 1024 threads
    __shared__ int warpsum[32];
    const int CH = 20;
    int t = threadIdx.x;
    int lane = t & 31, wid = t >> 5;
    int base = t * CH;
    int raw[CH];
    bool full = (base + CH <= N_NODES);
    if (full) {
#pragma unroll
        for (int v4 = 0; v4 < 5; v4++) {
            int4 v = *(const int4*)(g_count + base + v4 * 4);
            raw[v4 * 4 + 0] = v.x; raw[v4 * 4 + 1] = v.y;
            raw[v4 * 4 + 2] = v.z; raw[v4 * 4 + 3] = v.w;
        }
    } else {
#pragma unroll
        for (int j = 0; j < CH; j++)
            raw[j] = (base + j < N_NODES) ? g_count[base + j] : 0;
    }
    int vals[CH];
    int local = 0;
#pragma unroll
    for (int j = 0; j < CH; j++) { vals[j] = local; local += raw[j]; }
    int inc = local;
#pragma unroll
    for (int off = 1; off < 32; off <<= 1) {
        int v = __shfl_up_sync(0xffffffffu, inc, off);
        if (lane >= off) inc += v;
    }
    if (lane == 31) warpsum[wid] = inc;
    __syncthreads();
    if (wid == 0) {
        int v = warpsum[lane];
        int inc2 = v;
#pragma unroll
        for (int off = 1; off < 32; off <<= 1) {
            int u = __shfl_up_sync(0xffffffffu, inc2, off);
            if (lane >= off) inc2 += u;
        }
        warpsum[lane] = inc2 - v;
    }
    __syncthreads();
    int toff = warpsum[wid] + inc - local;
    if (full) {
#pragma unroll
        for (int v4 = 0; v4 < 5; v4++) {
            int4 st;
            st.x = toff + vals[v4 * 4 + 0];
            st.y = toff + vals[v4 * 4 + 1];
            st.z = toff + vals[v4 * 4 + 2];
            st.w = toff + vals[v4 * 4 + 3];
            *(int4*)(g_rowptr + base + v4 * 4) = st;
        }
    } else {
#pragma unroll
        for (int j = 0; j < CH; j++)
            if (base + j < N_NODES) g_rowptr[base + j] = toff + vals[j];
    }
    if (t == 1023) g_rowptr[N_NODES] = toff + local;
}

// fill: 4 edges per thread, vectorized loads
__global__ void k_fill(const void* ei) {
    int i = blockIdx.x * blockDim.x + threadIdx.x;
    if (i * 4 >= N_EDGES) return;
    int s0, s1, s2, s3, d0, d1, d2, d3;
    if (g_is64) {
        const longlong2* ps = (const longlong2*)ei;
        const longlong2* pd = (const longlong2*)((const long long*)ei + N_EDGES);
        longlong2 a = ps[i * 2], b = ps[i * 2 + 1];
        longlong2 c = pd[i * 2], d = pd[i * 2 + 1];
        s0 = (int)a.x; s1 = (int)a.y; s2 = (int)b.x; s3 = (int)b.y;
        d0 = (int)c.x; d1 = (int)c.y; d2 = (int)d.x; d3 = (int)d.y;
    } else {
        int4 a = ((const int4*)ei)[i];
        int4 c = ((const int4*)((const int*)ei + N_EDGES))[i];
        s0 = a.x; s1 = a.y; s2 = a.z; s3 = a.w;
        d0 = c.x; d1 = c.y; d2 = c.z; d3 = c.w;
    }
    g_srce[g_rowptr[d0] + atomicAdd(&g_fill[d0], 1)] = s0;
    g_srce[g_rowptr[d1] + atomicAdd(&g_fill[d1], 1)] = s1;
    g_srce[g_rowptr[d2] + atomicAdd(&g_fill[d2], 1)] = s2;
    g_srce[g_rowptr[d3] + atomicAdd(&g_fill[d3], 1)] = s3;
}

// ---------------- layer 0: x-gather + outer-product GEMM1 + HMMA GEMM2 ----------
// 256 threads = 8 warps, 1 node per warp.
__global__ void __launch_bounds__(256) k_layer0(
    const float* __restrict__ x, const float* __restrict__ w10,
    const float* __restrict__ b1, const float* __restrict__ b2) {
    __shared__ __half sW2[64 * WPAD];
    __shared__ __half sZ[8 * FEAT];
    __shared__ float sStats[128];
    __shared__ float sW10[64], sB1[64], sB2[64];
    __shared__ float sZ0[64];
    int t = threadIdx.x;
    int w = t >> 5, lane = t & 31;
    if (t < 128) sStats[t] = 0.f;
    if (t < 64) { sW10[t] = w10[t]; sB1[t] = b1[t]; sB2[t] = b2[t]; }
    const uint4* w2src = (const uint4*)g_W2h;   // layer 0 weights
#pragma unroll
    for (int rep = 0; rep < 2; rep++) {
        int j = t + rep * 256;
        int o = j >> 3, c8 = j & 7;
        ((uint4*)sW2)[o * 9 + c8] = w2src[j];
    }
    __syncthreads();   // sW2 + sW10/sB1/sB2 staged; warps proceed independently

    int n = (blockIdx.x << 3) + w;
    // gather z0[m]: 4 lane-groups split the edge range, shfl-reduce
    int m = lane & 7, g = lane >> 3;
    int rs = g_rowptr[n], re = g_rowptr[n + 1];
    float z = (g == 0) ? x[n * 8 + m] : 0.f;
    for (int e = rs + g; e < re; e += 4)
        z += x[g_srce[e] * 8 + m];
    z += __shfl_xor_sync(0xffffffffu, z, 8);
    z += __shfl_xor_sync(0xffffffffu, z, 16);
    if (lane < 8) sZ0[w * 8 + m] = z;
    __syncwarp();
    float zf[8];
#pragma unroll
    for (int j = 0; j < 8; j++) zf[j] = sZ0[w * 8 + j];
    // GEMM1 outer product: y[o][m] = relu(w10[o]*z0[m]+b1[o]) -> fp16 tile
    int orow0 = lane * 2;
#pragma unroll
    for (int r2 = 0; r2 < 2; r2++) {
        int o = orow0 + r2;
        float wv = sW10[o], b = sB1[o];
        __half2 p0 = __floats2half2_rn(fmaxf(wv * zf[0] + b, 0.f), fmaxf(wv * zf[1] + b, 0.f));
        __half2 p1 = __floats2half2_rn(fmaxf(wv * zf[2] + b, 0.f), fmaxf(wv * zf[3] + b, 0.f));
        __half2 p2 = __floats2half2_rn(fmaxf(wv * zf[4] + b, 0.f), fmaxf(wv * zf[5] + b, 0.f));
        __half2 p3 = __floats2half2_rn(fmaxf(wv * zf[6] + b, 0.f), fmaxf(wv * zf[7] + b, 0.f));
        uint4 hv;
        hv.x = *(unsigned*)&p0; hv.y = *(unsigned*)&p1;
        hv.z = *(unsigned*)&p2; hv.w = *(unsigned*)&p3;
        *(uint4*)(sZ + (w << 9) + o * 8) = hv;
    }
    __syncwarp();

    // GEMM2 (HMMA, padded weights)
    uint32_t zbase = smem_u32(sZ + w * FEAT);
    int r = lane >> 2, q = lane & 3;
    int arow = lane & 15, acol = (lane >> 4) << 3;
    unsigned bf[4][2];
#pragma unroll
    for (int k = 0; k < 4; k++)
        ldmBt(bf[k], zbase + ((k * 16 + (lane & 15)) * 8) * 2);
    uint32_t w2base = smem_u32(sW2);
    float acc[4][4];
#pragma unroll
    for (int ot = 0; ot < 4; ot++) {
#pragma unroll
        for (int i = 0; i < 4; i++) acc[ot][i] = 0.f;
#pragma unroll
        for (int k = 0; k < 4; k++) {
            unsigned af[4];
            ldmA(af, w2base + (ot * 16 + arow) * (WPAD * 2) + (k * 16 + acol) * 2);
            mma16816(acc[ot], af, bf[k]);
        }
    }
    // epilogue: h = relu(acc + b2) -> global fp16 + stats
    __half* hrow = g_hbuf + (size_t)n * FEAT;
#pragma unroll
    for (int ot = 0; ot < 4; ot++) {
        int oa = ot * 16 + r, ob = oa + 8;
        float ba = sB2[oa], bb = sB2[ob];
        float f0 = fmaxf(acc[ot][0] + ba, 0.f), f1 = fmaxf(acc[ot][1] + ba, 0.f);
        float f2 = fmaxf(acc[ot][2] + bb, 0.f), f3 = fmaxf(acc[ot][3] + bb, 0.f);
        *(__half2*)(hrow + oa * 8 + 2 * q) = __floats2half2_rn(f0, f1);
        *(__half2*)(hrow + ob * 8 + 2 * q) = __floats2half2_rn(f2, f3);
        float sa = f0 + f1, qa = f0 * f0 + f1 * f1;
        float sb = f2 + f3, qb = f2 * f2 + f3 * f3;
        sa += __shfl_xor_sync(0xffffffffu, sa, 1); sa += __shfl_xor_sync(0xffffffffu, sa, 2);
        qa += __shfl_xor_sync(0xffffffffu, qa, 1); qa += __shfl_xor_sync(0xffffffffu, qa, 2);
        sb += __shfl_xor_sync(0xffffffffu, sb, 1); sb += __shfl_xor_sync(0xffffffffu, sb, 2);
        qb += __shfl_xor_sync(0xffffffffu, qb, 1); qb += __shfl_xor_sync(0xffffffffu, qb, 2);
        if (q == 0) {
            atomicAdd(&sStats[oa], sa);
            atomicAdd(&sStats[64 + oa], qa);
            atomicAdd(&sStats[ob], sb);
            atomicAdd(&sStats[64 + ob], qb);
        }
    }
    __syncthreads();
    if (t < 128) atomicAdd(&g_stats[t], sStats[t]);
}

// ---------------- gather (layers 1..4): fp16 CSR gather + local BN affine ----
__device__ __forceinline__ void acc8(float a[8], uint4 v) {
    float2 p;
    p = __half22float2(*(const __half2*)&v.x); a[0] += p.x; a[1] += p.y;
    p = __half22float2(*(const __half2*)&v.y); a[2] += p.x; a[3] += p.y;
    p = __half22float2(*(const __half2*)&v.z); a[4] += p.x; a[5] += p.y;
    p = __half22float2(*(const __half2*)&v.w); a[6] += p.x; a[7] += p.y;
}

__global__ void __launch_bounds__(256) k_gather(
    int layer, const float* __restrict__ gamma, const float* __restrict__ beta) {
    __shared__ float sSc[64], sSh[64];
    const uint4* __restrict__ in = (const uint4*)g_hbuf;
    int t = threadIdx.x;
    if (t < 64) {
        const float* st = g_stats + (layer - 1) * 128;
        float inv = 1.0f / 160000.0f;
        float mean = st[t] * inv;
        float var = st[64 + t] * inv - mean * mean;
        float sc = gamma[t] * rsqrtf(var + 1e-5f);
        sSc[t] = sc;
        sSh[t] = beta[t] - mean * sc;
    }
    __syncthreads();
    int grp = t >> 6;
    int l = t & 63;
    int n = (blockIdx.x << 2) + grp;
    int rs = g_rowptr[n], re = g_rowptr[n + 1];
    float sc = sSc[l], sh = sSh[l];
    float a[8] = {0,0,0,0,0,0,0,0}, b[8] = {0,0,0,0,0,0,0,0};
    acc8(a, in[(size_t)n * 64 + l]);   // self
    int e = rs;
    for (; e + 4 <= re; e += 4) {
        uint4 v0 = in[(size_t)g_srce[e]     * 64 + l];
        uint4 v1 = in[(size_t)g_srce[e + 1] * 64 + l];
        uint4 v2 = in[(size_t)g_srce[e + 2] * 64 + l];
        uint4 v3 = in[(size_t)g_srce[e + 3] * 64 + l];
        acc8(a, v0); acc8(b, v1); acc8(a, v2); acc8(b, v3);
    }
    for (; e < re; e++) acc8(a, in[(size_t)g_srce[e] * 64 + l]);
    float shd = sh * (float)(re - rs + 1);
    float f0 = sc * (a[0] + b[0]) + shd, f1 = sc * (a[1] + b[1]) + shd;
    float f2 = sc * (a[2] + b[2]) + shd, f3 = sc * (a[3] + b[3]) + shd;
    float f4 = sc * (a[4] + b[4]) + shd, f5 = sc * (a[5] + b[5]) + shd;
    float f6 = sc * (a[6] + b[6]) + shd, f7 = sc * (a[7] + b[7]) + shd;
    __half2 h0 = __floats2half2_rn(f0, f1);
    __half2 h1 = __floats2half2_rn(f2, f3);
    __half2 h2 = __floats2half2_rn(f4, f5);
    __half2 h3 = __floats2half2_rn(f6, f7);
    uint4 hv;
    hv.x = *(unsigned*)&h0; hv.y = *(unsigned*)&h1;
    hv.z = *(unsigned*)&h2; hv.w = *(unsigned*)&h3;
    *(uint4*)(g_z16 + (size_t)n * FEAT + (l << 3)) = hv;
}

// ---------------- MLP (layers 1..4): HMMA GEMM pair, padded weight smem ----
// Layer 4 also accumulates the global mean-pool in its epilogue.
__global__ void __launch_bounds__(256) k_mlp(
    int layer, const float* __restrict__ b1, const float* __restrict__ b2) {
    __shared__ __half sW1[64 * WPAD];
    __shared__ __half sW2[64 * WPAD];
    __shared__ __half sZ[8 * FEAT];
    __shared__ float sStats[128];
    __shared__ float sPool[FEAT];
    __shared__ float sB1[64], sB2[64];
    int t = threadIdx.x;
    int w = t >> 5, lane = t & 31;
    if (t < 128) sStats[t] = 0.f;
    if (t < 64) { sB1[t] = b1[t]; sB2[t] = b2[t]; }
    if (layer == 4) { sPool[t] = 0.f; sPool[t + 256] = 0.f; }
    const uint4* w1src = (const uint4*)(g_W1h + (size_t)(layer - 1) * 4096);
    const uint4* w2src = (const uint4*)(g_W2h + (size_t)layer * 4096);
    const uint4* zsrc  = (const uint4*)(g_z16 + (size_t)(blockIdx.x << 3) * FEAT);
#pragma unroll
    for (int rep = 0; rep < 2; rep++) {
        int j = t + rep * 256;
        int o = j >> 3, c8 = j & 7;
        ((uint4*)sW1)[o * 9 + c8] = w1src[j];
        ((uint4*)sW2)[o * 9 + c8] = w2src[j];
    }
    ((uint4*)sZ)[t]       = zsrc[t];
    ((uint4*)sZ)[t + 256] = zsrc[t + 256];
    __syncthreads();

    int n = (blockIdx.x << 3) + w;
    uint32_t zbase = smem_u32(sZ + w * FEAT);
    int r = lane >> 2, q = lane & 3;
    int arow = lane & 15, acol = (lane >> 4) << 3;

    // ---- GEMM1 ----
    unsigned bf[4][2];
#pragma unroll
    for (int k = 0; k < 4; k++)
        ldmBt(bf[k], zbase + ((k * 16 + (lane & 15)) * 8) * 2);
    uint32_t w1base = smem_u32(sW1);
    float acc[4][4];
#pragma unroll
    for (int ot = 0; ot < 4; ot++) {
#pragma unroll
        for (int i = 0; i < 4; i++) acc[ot][i] = 0.f;
#pragma unroll
        for (int k = 0; k < 4; k++) {
            unsigned af[4];
            ldmA(af, w1base + (ot * 16 + arow) * (WPAD * 2) + (k * 16 + acol) * 2);
            mma16816(acc[ot], af, bf[k]);
        }
    }
#pragma unroll
    for (int ot = 0; ot < 4; ot++) {
        int oa = ot * 16 + r, ob = oa + 8;
        float ba = sB1[oa], bb = sB1[ob];
        __half2 ya = __floats2half2_rn(fmaxf(acc[ot][0] + ba, 0.f), fmaxf(acc[ot][1] + ba, 0.f));
        __half2 yb = __floats2half2_rn(fmaxf(acc[ot][2] + bb, 0.f), fmaxf(acc[ot][3] + bb, 0.f));
        *(__half2*)(sZ + w * FEAT + oa * 8 + 2 * q) = ya;
        *(__half2*)(sZ + w * FEAT + ob * 8 + 2 * q) = yb;
    }
    __syncwarp();

    // ---- GEMM2 ----
#pragma unroll
    for (int k = 0; k < 4; k++)
        ldmBt(bf[k], zbase + ((k * 16 + (lane & 15)) * 8) * 2);
    uint32_t w2base = smem_u32(sW2);
#pragma unroll
    for (int ot = 0; ot < 4; ot++) {
#pragma unroll
        for (int i = 0; i < 4; i++) acc[ot][i] = 0.f;
#pragma unroll
        for (int k = 0; k < 4; k++) {
            unsigned af[4];
            ldmA(af, w2base + (ot * 16 + arow) * (WPAD * 2) + (k * 16 + acol) * 2);
            mma16816(acc[ot], af, bf[k]);
        }
    }
    __half* hrow = g_hbuf + (size_t)n * FEAT;
#pragma unroll
    for (int ot = 0; ot < 4; ot++) {
        int oa = ot * 16 + r, ob = oa + 8;
        float ba = sB2[oa], bb = sB2[ob];
        float f0 = fmaxf(acc[ot][0] + ba, 0.f), f1 = fmaxf(acc[ot][1] + ba, 0.f);
        float f2 = fmaxf(acc[ot][2] + bb, 0.f), f3 = fmaxf(acc[ot][3] + bb, 0.f);
        *(__half2*)(hrow + oa * 8 + 2 * q) = __floats2half2_rn(f0, f1);
        *(__half2*)(hrow + ob * 8 + 2 * q) = __floats2half2_rn(f2, f3);
        if (layer == 4) {
            atomicAdd(&sPool[oa * 8 + 2 * q],     f0);
            atomicAdd(&sPool[oa * 8 + 2 * q + 1], f1);
            atomicAdd(&sPool[ob * 8 + 2 * q],     f2);
            atomicAdd(&sPool[ob * 8 + 2 * q + 1], f3);
        }
        float sa = f0 + f1, qa = f0 * f0 + f1 * f1;
        float sb = f2 + f3, qb = f2 * f2 + f3 * f3;
        sa += __shfl_xor_sync(0xffffffffu, sa, 1); sa += __shfl_xor_sync(0xffffffffu, sa, 2);
        qa += __shfl_xor_sync(0xffffffffu, qa, 1); qa += __shfl_xor_sync(0xffffffffu, qa, 2);
        sb += __shfl_xor_sync(0xffffffffu, sb, 1); sb += __shfl_xor_sync(0xffffffffu, sb, 2);
        qb += __shfl_xor_sync(0xffffffffu, qb, 1); qb += __shfl_xor_sync(0xffffffffu, qb, 2);
        if (q == 0) {
            atomicAdd(&sStats[oa], sa);
            atomicAdd(&sStats[64 + oa], qa);
            atomicAdd(&sStats[ob], sb);
            atomicAdd(&sStats[64 + ob], qb);
        }
    }
    __syncthreads();
    if (t < 128) atomicAdd(&g_stats[layer * 128 + t], sStats[t]);
    if (layer == 4) {
        atomicAdd(&g_pool[t], sPool[t]);
        atomicAdd(&g_pool[t + 256], sPool[t + 256]);
    }
}

// ---------------- head ----------------
__global__ void k_final(const float* __restrict__ gamma, const float* __restrict__ beta,
                        const float* __restrict__ wout, const float* __restrict__ bout,
                        float* __restrict__ o) {
    __shared__ float sSc[64], sSh[64];
    int t = threadIdx.x;   // 64 threads
    {
        const float* st = g_stats + 4 * 128;
        float inv = 1.0f / 160000.0f;
        float mean = st[t] * inv;
        float var = st[64 + t] * inv - mean * mean;
        float sc = gamma[t] * rsqrtf(var + 1e-5f);
        sSc[t] = sc;
        sSh[t] = beta[t] - mean * sc;
    }
    __syncthreads();
    if (t < 8) {
        float acc = bout[0];
        for (int c = 0; c < 64; c++)
            acc += wout[c] * (sSc[c] * g_pool[c * 8 + t] * (1.0f / N_NODES) + sSh[c]);
        o[t] = 1.0f / (1.0f + expf(-acc));
    }
}

// ---------------- launch ----------------
extern "C" void kernel_launch(void* const* d_in, const int* in_sizes, int n_in,
                              void* d_out, int out_size) {
    const float* x     = (const float*)d_in[0];
    const void*  ei    = d_in[1];
    // d_in[2] = batch (unused, all zeros)
    const float* w10   = (const float*)d_in[3];
    const float* w1    = (const float*)d_in[4];
    const float* b1    = (const float*)d_in[5];
    const float* w2    = (const float*)d_in[6];
    const float* b2    = (const float*)d_in[7];
    const float* gamma = (const float*)d_in[8];
    const float* beta  = (const float*)d_in[9];
    const float* wout  = (const float*)d_in[10];
    const float* bout  = (const float*)d_in[11];
    float* out = (float*)d_out;

    k_init<<<(5 * 4096 + 255) / 256, 256>>>(ei, w1, w2);   // 80 blocks covers all init work
    k_hist<<<(N_EDGES / 4 + 255) / 256, 256>>>(ei);
    k_scan<<<1, 1024>>>();
    k_fill<<<(N_EDGES / 4 + 255) / 256, 256>>>(ei);

    k_layer0<<<N_NODES / 8, 256>>>(x, w10, b1, b2);
    for (int i = 1; i <= 4; i++) {
        k_gather<<<N_NODES / 4, 256>>>(i, gamma + (i - 1) * 64, beta + (i - 1) * 64);
        k_mlp<<<N_NODES / 8, 256>>>(i, b1 + i * 64, b2 + i * 64);
    }
    k_final<<<1, 64>>>(gamma + 4 * 64, beta + 4 * 64, wout, bout, out);
}